// round 14
// baseline (speedup 1.0000x reference)
#include <cuda_runtime.h>
#include <cuda_bf16.h>
#include <cstdint>

// ---------------- problem constants ----------------
#define NLAT   181
#define NLON   360
#define NV     78
#define NGRID  (NLAT*NLON)      // 65160
#define NBATCH 2
#define NMESH  10242
#define NEDGE  163840
#define NODE_D 256
#define EDGE_D 64
#define HIDD   512
#define NLAYERS 16
#define ENC_IN  163
#define ENC_LDA 164

// ---------------- device scratch ----------------
__device__ float g_encin[(size_t)NBATCH*NMESH*ENC_LDA];
__device__ float g_x    [(size_t)NBATCH*NMESH*NODE_D];
__device__ float g_e    [(size_t)NBATCH*NEDGE*EDGE_D];
__device__ float g_e0   [(size_t)NEDGE*EDGE_D];
__device__ float g_h    [(size_t)NEDGE*HIDD];
__device__ float g_agg  [(size_t)NBATCH*NMESH*EDGE_D];
__device__ float g_xsd  [(size_t)NBATCH*NMESH*1024];
__device__ float g_zeros[1024];
__device__ float g_dcb2p[80];
// edge sort (dst-sorted order; edge state lives in sorted space forever)
__device__ int   g_cnt  [NMESH];
__device__ int   g_off  [NMESH];
__device__ int   g_srcS [NEDGE];
__device__ int   g_dstS [NEDGE];
__device__ float g_redgeS[(size_t)NEDGE*4];
// bf16 hi/lo split weights
__device__ __nv_bfloat16 g_pe1hi[(size_t)NLAYERS*576*HIDD];
__device__ __nv_bfloat16 g_pe1lo[(size_t)NLAYERS*576*HIDD];
__device__ __nv_bfloat16 g_wsdhi[(size_t)NLAYERS*256*1024];
__device__ __nv_bfloat16 g_wsdlo[(size_t)NLAYERS*256*1024];
__device__ __nv_bfloat16 g_pe2hi[(size_t)NLAYERS*HIDD*EDGE_D];
__device__ __nv_bfloat16 g_pe2lo[(size_t)NLAYERS*HIDD*EDGE_D];
__device__ __nv_bfloat16 g_pn1hi[(size_t)NLAYERS*320*HIDD];
__device__ __nv_bfloat16 g_pn1lo[(size_t)NLAYERS*320*HIDD];
__device__ __nv_bfloat16 g_pn2hi[(size_t)NLAYERS*HIDD*NODE_D];
__device__ __nv_bfloat16 g_pn2lo[(size_t)NLAYERS*HIDD*NODE_D];
__device__ __nv_bfloat16 g_dc1hi[(size_t)NODE_D*HIDD];
__device__ __nv_bfloat16 g_dc1lo[(size_t)NODE_D*HIDD];
__device__ __nv_bfloat16 g_dc2hi[(size_t)HIDD*80];
__device__ __nv_bfloat16 g_dc2lo[(size_t)HIDD*80];
__device__ __nv_bfloat16 g_en2hi[(size_t)HIDD*NODE_D];
__device__ __nv_bfloat16 g_en2lo[(size_t)HIDD*NODE_D];
__device__ __nv_bfloat16 g_em2hi[(size_t)EDGE_D*EDGE_D];
__device__ __nv_bfloat16 g_em2lo[(size_t)EDGE_D*EDGE_D];

// ---------------- asm helpers ----------------
__device__ __forceinline__ void ldsm_x4(uint32_t* r, uint32_t addr) {
    asm volatile("ldmatrix.sync.aligned.m8n8.x4.shared.b16 {%0,%1,%2,%3}, [%4];"
        : "=r"(r[0]), "=r"(r[1]), "=r"(r[2]), "=r"(r[3]) : "r"(addr));
}
__device__ __forceinline__ void ldsm_x4t(uint32_t* r, uint32_t addr) {
    asm volatile("ldmatrix.sync.aligned.m8n8.x4.trans.shared.b16 {%0,%1,%2,%3}, [%4];"
        : "=r"(r[0]), "=r"(r[1]), "=r"(r[2]), "=r"(r[3]) : "r"(addr));
}
__device__ __forceinline__ void mma16816(float* d, const uint32_t* a, const uint32_t* b) {
    asm volatile("mma.sync.aligned.m16n8k16.row.col.f32.bf16.bf16.f32 "
        "{%0,%1,%2,%3}, {%4,%5,%6,%7}, {%8,%9}, {%0,%1,%2,%3};"
        : "+f"(d[0]), "+f"(d[1]), "+f"(d[2]), "+f"(d[3])
        : "r"(a[0]), "r"(a[1]), "r"(a[2]), "r"(a[3]), "r"(b[0]), "r"(b[1]));
}
__device__ __forceinline__ uint32_t smem_u32(const void* p) {
    uint32_t a;
    asm("{ .reg .u64 t; cvta.to.shared.u64 t, %1; cvt.u32.u64 %0, t; }" : "=r"(a) : "l"(p));
    return a;
}
#define CP_ASYNC16(dst, src) \
    asm volatile("cp.async.cg.shared.global [%0], [%1], 16;" :: "r"(dst), "l"(src))
#define CP_COMMIT() asm volatile("cp.async.commit_group;" ::: "memory")
#define CP_WAIT0()  asm volatile("cp.async.wait_group 0;" ::: "memory")
#define STS_V2(addr, x, y) \
    asm volatile("st.shared.v2.u32 [%0], {%1,%2};" :: "r"(addr), "r"(x), "r"(y))
#define STS_U32(addr, x) \
    asm volatile("st.shared.u32 [%0], %1;" :: "r"(addr), "r"(x))

__device__ __forceinline__ void split4(float4 v, uint2& hh, uint2& ll) {
    __nv_bfloat16 h0 = __float2bfloat16_rn(v.x), h1 = __float2bfloat16_rn(v.y);
    __nv_bfloat16 h2 = __float2bfloat16_rn(v.z), h3 = __float2bfloat16_rn(v.w);
    __nv_bfloat16 g0 = __float2bfloat16_rn(v.x - __bfloat162float(h0));
    __nv_bfloat16 g1 = __float2bfloat16_rn(v.y - __bfloat162float(h1));
    __nv_bfloat16 g2 = __float2bfloat16_rn(v.z - __bfloat162float(h2));
    __nv_bfloat16 g3 = __float2bfloat16_rn(v.w - __bfloat162float(h3));
    hh.x = (uint32_t)__bfloat16_as_ushort(h0) | ((uint32_t)__bfloat16_as_ushort(h1) << 16);
    hh.y = (uint32_t)__bfloat16_as_ushort(h2) | ((uint32_t)__bfloat16_as_ushort(h3) << 16);
    ll.x = (uint32_t)__bfloat16_as_ushort(g0) | ((uint32_t)__bfloat16_as_ushort(g1) << 16);
    ll.y = (uint32_t)__bfloat16_as_ushort(g2) | ((uint32_t)__bfloat16_as_ushort(g3) << 16);
}
__device__ __forceinline__ void split2(float vx, float vy, uint32_t& hp, uint32_t& lp) {
    __nv_bfloat16 hx = __float2bfloat16_rn(vx), hy = __float2bfloat16_rn(vy);
    __nv_bfloat16 lx = __float2bfloat16_rn(vx - __bfloat162float(hx));
    __nv_bfloat16 ly = __float2bfloat16_rn(vy - __bfloat162float(hy));
    hp = (uint32_t)__bfloat16_as_ushort(hx) | ((uint32_t)__bfloat16_as_ushort(hy) << 16);
    lp = (uint32_t)__bfloat16_as_ushort(lx) | ((uint32_t)__bfloat16_as_ushort(ly) << 16);
}

// ---------------- A-gather modes ----------------
// MODE 0: plain A[M][K]
// MODE 2: [x(256)|agg(64)]
// MODE 4: gathered rows A[m2g[g%NGRID] + (g/NGRID)*NMESH][256]
template<int MODE, int AIT, int RPI>
__device__ __forceinline__ void prefA(float4 (&Ra)[AIT], int c, int rowBase, int M,
    const float* __restrict__ A, const float* __restrict__ aux,
    const int (&sI)[AIT], int tid, int K)
{
    const int f = tid & 15;
    #pragma unroll
    for (int it = 0; it < AIT; it++) {
        int gr = rowBase + it * RPI + (tid >> 4);
        if (gr < M) {
            const float* p;
            if (MODE == 0)      p = A + (size_t)gr * K + c * 64;
            else if (MODE == 2) p = (c < 4) ? A + (size_t)gr * 256 + c * 64
                                            : aux + (size_t)gr * 64;
            else                p = A + (size_t)sI[it] * 256 + c * 64;
            Ra[it] = reinterpret_cast<const float4*>(p)[f];
        } else {
            Ra[it] = make_float4(0.f, 0.f, 0.f, 0.f);
        }
    }
}

// =====================================================================
//  HMMA GEMM: C[M x Nclip (pitch Cpitch)] = [res+] relu?(gather(A)@W + bias)
//  BN=64 + MINB=2 -> 110.6 KB smem, 2 CTAs/SM (cross-CTA latency hiding).
//  ZAGG: CTAs in column 0 also zero zbuf rows.
// =====================================================================
template<int THREADS, int MINB, int BN, int WARPS_N, int NC, int MODE,
         bool RELU, bool HAS_RES, bool ZAGG>
__global__ void __launch_bounds__(THREADS, MINB)
mma_gemm(const float* __restrict__ A, const float* __restrict__ aux,
         const int* __restrict__ idx1,
         const __nv_bfloat16* __restrict__ Bhi, const __nv_bfloat16* __restrict__ Blo,
         const float* __restrict__ bias, const float* res, float* C,
         float* zbuf, int M, int Nfull, int Cpitch, int Nclip)
{
    constexpr int K       = NC * 64;
    constexpr int NWARP   = THREADS / 32;
    constexpr int WARPS_M = NWARP / WARPS_N;
    constexpr int WTM     = 128 / WARPS_M;
    constexpr int WTN     = BN / WARPS_N;
    constexpr int MT      = WTM / 16;
    constexpr int NT      = WTN / 8;
    constexpr int ASTRIDE = 72;
    constexpr int APLANE  = 128 * ASTRIDE * 2;
    constexpr int ABUF    = 2 * APLANE;
    constexpr int BSTRIDE = BN + 8;
    constexpr int BPLANE  = 64 * BSTRIDE * 2;
    constexpr int BBUF    = 2 * BPLANE;
    constexpr int GRAN    = BN / 8;
    constexpr int BTOT    = 2 * 64 * GRAN;
    constexpr int AIT     = 2048 / THREADS;
    constexpr int RPI     = THREADS / 16;
    static_assert((BTOT % THREADS) == 0, "B loader divisibility");

    extern __shared__ char sm[];
    const uint32_t smA = smem_u32(sm);
    const uint32_t smB = smA + 2 * ABUF;

    const int tid    = threadIdx.x;
    const int lane   = tid & 31;
    const int wid    = tid >> 5;
    const int warp_n = wid % WARPS_N;
    const int warp_m = wid / WARPS_N;
    const int rowBase = blockIdx.y * 128;
    const int colBase = blockIdx.x * BN;

    if (ZAGG && blockIdx.x == 0) {
        #pragma unroll
        for (int it = 0; it < 2048 / THREADS; it++) {
            int i = tid + it * THREADS;
            int r = rowBase + (i >> 4);
            if (r < M)
                reinterpret_cast<float4*>(zbuf)[(size_t)r * 16 + (i & 15)] =
                    make_float4(0.f, 0.f, 0.f, 0.f);
        }
    }

    int sI[AIT];
    #pragma unroll
    for (int it = 0; it < AIT; it++) {
        int gr = rowBase + it * RPI + (tid >> 4);
        int g  = (gr < M) ? gr : 0;
        if (MODE == 4) {
            int b = g / NGRID;
            sI[it] = idx1[g - b * NGRID] + b * NMESH;
        } else {
            sI[it] = 0;
        }
    }

    float acc[MT][NT][4];
    #pragma unroll
    for (int i = 0; i < MT; i++)
        #pragma unroll
        for (int j = 0; j < NT; j++)
            #pragma unroll
            for (int q = 0; q < 4; q++) acc[i][j][q] = 0.f;

    float4 Ra[AIT];
    prefA<MODE, AIT, RPI>(Ra, 0, rowBase, M, A, aux, sI, tid, K);

    {
        #pragma unroll
        for (int it = 0; it < BTOT / THREADS; it++) {
            int i = it * THREADS + tid;
            int plane = i / (64 * GRAN);
            int rem   = i % (64 * GRAN);
            int k = rem / GRAN, g = rem % GRAN;
            const __nv_bfloat16* sp = (plane ? Blo : Bhi)
                + (size_t)k * Nfull + colBase + g * 8;
            CP_ASYNC16(smB + plane * BPLANE + (uint32_t)(k * BSTRIDE + g * 8) * 2, sp);
        }
        CP_COMMIT();
    }

    for (int c = 0; c < NC; c++) {
        const int buf = c & 1;
        #pragma unroll
        for (int it = 0; it < AIT; it++) {
            int r = it * RPI + (tid >> 4);
            int f = tid & 15;
            uint2 hh, ll;
            split4(Ra[it], hh, ll);
            uint32_t off = smA + buf * ABUF + (uint32_t)(r * ASTRIDE + f * 4) * 2;
            STS_V2(off, hh.x, hh.y);
            STS_V2(off + APLANE, ll.x, ll.y);
        }
        if (c + 1 < NC) prefA<MODE, AIT, RPI>(Ra, c + 1, rowBase, M, A, aux, sI, tid, K);
        CP_WAIT0();
        __syncthreads();
        if (c + 1 < NC) {
            #pragma unroll
            for (int it = 0; it < BTOT / THREADS; it++) {
                int i = it * THREADS + tid;
                int plane = i / (64 * GRAN);
                int rem   = i % (64 * GRAN);
                int k = rem / GRAN, g = rem % GRAN;
                const __nv_bfloat16* sp = (plane ? Blo : Bhi)
                    + (size_t)(c + 1) * 64 * Nfull + (size_t)k * Nfull + colBase + g * 8;
                CP_ASYNC16(smB + (1 - buf) * BBUF + plane * BPLANE
                           + (uint32_t)(k * BSTRIDE + g * 8) * 2, sp);
            }
            CP_COMMIT();
        }

        #pragma unroll
        for (int ks = 0; ks < 4; ks++) {
            uint32_t Ah[MT][4], Al[MT][4];
            #pragma unroll
            for (int mt = 0; mt < MT; mt++) {
                uint32_t addr = smA + buf * ABUF
                    + (uint32_t)((warp_m * WTM + mt * 16 + (lane & 15)) * ASTRIDE
                                 + ks * 16 + (lane >> 4) * 8) * 2;
                ldsm_x4(Ah[mt], addr);
                ldsm_x4(Al[mt], addr + APLANE);
            }
            uint32_t Bh[(NT + 1) / 2][4], Bl[(NT + 1) / 2][4];
            #pragma unroll
            for (int np = 0; np < NT / 2; np++) {
                uint32_t addr = smB + buf * BBUF
                    + (uint32_t)((ks * 16 + (lane & 15)) * BSTRIDE
                                 + warp_n * WTN + np * 16 + (lane >> 4) * 8) * 2;
                ldsm_x4t(Bh[np], addr);
                ldsm_x4t(Bl[np], addr + BPLANE);
            }
            #pragma unroll
            for (int mt = 0; mt < MT; mt++)
                #pragma unroll
                for (int nt = 0; nt < NT; nt++) {
                    const uint32_t* bh = &Bh[nt >> 1][(nt & 1) * 2];
                    const uint32_t* bl = &Bl[nt >> 1][(nt & 1) * 2];
                    mma16816(acc[mt][nt], Ah[mt], bh);
                    mma16816(acc[mt][nt], Ah[mt], bl);
                    mma16816(acc[mt][nt], Al[mt], bh);
                }
        }
    }

    #pragma unroll
    for (int nt = 0; nt < NT; nt++) {
        int n = colBase + warp_n * WTN + nt * 8 + (lane & 3) * 2;
        if (n >= Nclip) continue;
        float2 bb = *reinterpret_cast<const float2*>(bias + n);
        #pragma unroll
        for (int mt = 0; mt < MT; mt++) {
            #pragma unroll
            for (int half = 0; half < 2; half++) {
                int row = rowBase + warp_m * WTM + mt * 16 + (lane >> 2) + half * 8;
                if (row < M) {
                    float vx = acc[mt][nt][half * 2 + 0] + bb.x;
                    float vy = acc[mt][nt][half * 2 + 1] + bb.y;
                    size_t off = (size_t)row * Cpitch + n;
                    if (HAS_RES) {
                        float2 rr = *reinterpret_cast<const float2*>(res + off);
                        vx += rr.x; vy += rr.y;
                    }
                    if (RELU) { vx = fmaxf(vx, 0.f); vy = fmaxf(vy, 0.f); }
                    float2 o; o.x = vx; o.y = vy;
                    *reinterpret_cast<float2*>(C + off) = o;
                }
            }
        }
    }
}

// =====================================================================
//  Fused edge layer (batched via blockIdx.y, edges dst-sorted):
//  256 threads / 8 warps, 110.6 KB smem -> 2 CTAs/SM.
// =====================================================================
__global__ void __launch_bounds__(256, 2)
fused_edge(const float* __restrict__ ein,
           const float* __restrict__ xsd,
           const int* __restrict__ src, const int* __restrict__ dst,
           const __nv_bfloat16* __restrict__ W1hi, const __nv_bfloat16* __restrict__ W1lo,
           const __nv_bfloat16* __restrict__ W2hi, const __nv_bfloat16* __restrict__ W2lo,
           const float* __restrict__ b1, const float* __restrict__ b2,
           float* __restrict__ eout, float* __restrict__ agg,
           size_t einBatchStride)
{
    constexpr int A_STR  = 72;
    constexpr int A_PL   = 128 * A_STR * 2;
    constexpr int OFF_A  = 0;
    constexpr int B1_STR = 72;
    constexpr int B1_PL  = 64 * B1_STR * 2;
    constexpr int OFF_B1 = 2 * A_PL;
    constexpr int H_STR  = 72;
    constexpr int H_PL   = 128 * H_STR * 2;
    constexpr int OFF_H  = OFF_B1 + 2 * B1_PL;
    constexpr int B2_STR = 72;
    constexpr int B2_PL  = 64 * B2_STR * 2;
    constexpr int OFF_B2 = OFF_H + 2 * H_PL;   // total 110592

    extern __shared__ char sm[];
    const uint32_t base = smem_u32(sm);

    const int tid  = threadIdx.x;
    const int lane = tid & 31;
    const int wid  = tid >> 5;
    const int warp_m = wid >> 1;
    const int warp_n = wid & 1;
    const int rowBase = blockIdx.x * 128;
    const int batch   = blockIdx.y;

    const float* einb = ein + (size_t)batch * einBatchStride;
    const float* xsdb = xsd + (size_t)batch * NMESH * 1024;
    float* eoutb = eout + (size_t)batch * NEDGE * EDGE_D;
    float* aggb  = agg  + (size_t)batch * NMESH * EDGE_D;

    int sidx[2][2], didx[2][2];
    #pragma unroll
    for (int mt = 0; mt < 2; mt++)
        #pragma unroll
        for (int half = 0; half < 2; half++) {
            int g = rowBase + warp_m * 32 + mt * 16 + (lane >> 2) + half * 8;
            sidx[mt][half] = src[g];
            didx[mt][half] = dst[g];
        }

    {
        const float4* E4 = reinterpret_cast<const float4*>(einb + (size_t)rowBase * 64);
        #pragma unroll
        for (int it = 0; it < 8; it++) {
            int i = tid + it * 256;
            int r = i >> 4, f = i & 15;
            float4 v = E4[r * 16 + f];
            uint2 hh, ll;
            split4(v, hh, ll);
            uint32_t off = base + OFF_A + (uint32_t)(r * A_STR + f * 4) * 2;
            STS_V2(off, hh.x, hh.y);
            STS_V2(off + A_PL, ll.x, ll.y);
        }
    }

    float acc2[2][4][4];
    #pragma unroll
    for (int i = 0; i < 2; i++)
        #pragma unroll
        for (int j = 0; j < 4; j++)
            #pragma unroll
            for (int q = 0; q < 4; q++) acc2[i][j][q] = 0.f;

    for (int nc = 0; nc < 8; nc++) {
        __syncthreads();
        #pragma unroll
        for (int it = 0; it < 4; it++) {
            int i = tid + it * 256;
            int plane = i >> 9;
            int rem = i & 511;
            int k = rem >> 3, g = rem & 7;
            const __nv_bfloat16* sp = (plane ? W1lo : W1hi)
                + (size_t)k * 512 + nc * 64 + g * 8;
            CP_ASYNC16(base + OFF_B1 + plane * B1_PL + (uint32_t)(k * B1_STR + g * 8) * 2, sp);
        }
        #pragma unroll
        for (int it = 0; it < 4; it++) {
            int i = tid + it * 256;
            int plane = i >> 9;
            int rem = i & 511;
            int k = rem >> 3, g = rem & 7;
            const __nv_bfloat16* sp = (plane ? W2lo : W2hi)
                + (size_t)(nc * 64 + k) * 64 + g * 8;
            CP_ASYNC16(base + OFF_B2 + plane * B2_PL + (uint32_t)(k * B2_STR + g * 8) * 2, sp);
        }
        CP_COMMIT();
        CP_WAIT0();
        __syncthreads();

        float acc1[2][4][4];
        #pragma unroll
        for (int i = 0; i < 2; i++)
            #pragma unroll
            for (int j = 0; j < 4; j++)
                #pragma unroll
                for (int q = 0; q < 4; q++) acc1[i][j][q] = 0.f;

        #pragma unroll
        for (int ks = 0; ks < 4; ks++) {
            uint32_t Ah[2][4], Al[2][4];
            #pragma unroll
            for (int mt = 0; mt < 2; mt++) {
                uint32_t addr = base + OFF_A
                    + (uint32_t)((warp_m * 32 + mt * 16 + (lane & 15)) * A_STR
                                 + ks * 16 + (lane >> 4) * 8) * 2;
                ldsm_x4(Ah[mt], addr);
                ldsm_x4(Al[mt], addr + A_PL);
            }
            uint32_t Bh[2][4], Bl[2][4];
            #pragma unroll
            for (int np = 0; np < 2; np++) {
                uint32_t addr = base + OFF_B1
                    + (uint32_t)((ks * 16 + (lane & 15)) * B1_STR
                                 + warp_n * 32 + np * 16 + (lane >> 4) * 8) * 2;
                ldsm_x4t(Bh[np], addr);
                ldsm_x4t(Bl[np], addr + B1_PL);
            }
            #pragma unroll
            for (int mt = 0; mt < 2; mt++)
                #pragma unroll
                for (int nt = 0; nt < 4; nt++) {
                    const uint32_t* bh = &Bh[nt >> 1][(nt & 1) * 2];
                    const uint32_t* bl = &Bl[nt >> 1][(nt & 1) * 2];
                    mma16816(acc1[mt][nt], Ah[mt], bh);
                    mma16816(acc1[mt][nt], Ah[mt], bl);
                    mma16816(acc1[mt][nt], Al[mt], bh);
                }
        }

        #pragma unroll
        for (int nt = 0; nt < 4; nt++) {
            int col  = warp_n * 32 + nt * 8 + (lane & 3) * 2;
            int gcol = nc * 64 + col;
            float2 bb = *reinterpret_cast<const float2*>(b1 + gcol);
            #pragma unroll
            for (int mt = 0; mt < 2; mt++) {
                #pragma unroll
                for (int half = 0; half < 2; half++) {
                    int row_l = warp_m * 32 + mt * 16 + (lane >> 2) + half * 8;
                    float2 sv = *reinterpret_cast<const float2*>(
                        xsdb + (size_t)sidx[mt][half] * 1024 + gcol);
                    float2 dv = *reinterpret_cast<const float2*>(
                        xsdb + (size_t)didx[mt][half] * 1024 + 512 + gcol);
                    float vx = fmaxf(acc1[mt][nt][half * 2 + 0] + bb.x + sv.x + dv.x, 0.f);
                    float vy = fmaxf(acc1[mt][nt][half * 2 + 1] + bb.y + sv.y + dv.y, 0.f);
                    uint32_t hp, lp;
                    split2(vx, vy, hp, lp);
                    uint32_t off = base + OFF_H + (uint32_t)(row_l * H_STR + col) * 2;
                    STS_U32(off, hp);
                    STS_U32(off + H_PL, lp);
                }
            }
        }
        __syncthreads();

        #pragma unroll
        for (int ks = 0; ks < 4; ks++) {
            uint32_t Ah[2][4], Al[2][4];
            #pragma unroll
            for (int mt = 0; mt < 2; mt++) {
                uint32_t addr = base + OFF_H
                    + (uint32_t)((warp_m * 32 + mt * 16 + (lane & 15)) * H_STR
                                 + ks * 16 + (lane >> 4) * 8) * 2;
                ldsm_x4(Ah[mt], addr);
                ldsm_x4(Al[mt], addr + H_PL);
            }
            uint32_t Bh[2][4], Bl[2][4];
            #pragma unroll
            for (int np = 0; np < 2; np++) {
                uint32_t addr = base + OFF_B2
                    + (uint32_t)((ks * 16 + (lane & 15)) * B2_STR
                                 + warp_n * 32 + np * 16 + (lane >> 4) * 8) * 2;
                ldsm_x4t(Bh[np], addr);
                ldsm_x4t(Bl[np], addr + B2_PL);
            }
            #pragma unroll
            for (int mt = 0; mt < 2; mt++)
                #pragma unroll
                for (int nt = 0; nt < 4; nt++) {
                    const uint32_t* bh = &Bh[nt >> 1][(nt & 1) * 2];
                    const uint32_t* bl = &Bl[nt >> 1][(nt & 1) * 2];
                    mma16816(acc2[mt][nt], Ah[mt], bh);
                    mma16816(acc2[mt][nt], Ah[mt], bl);
                    mma16816(acc2[mt][nt], Al[mt], bh);
                }
        }
    }

    __syncthreads();
    float* stage = reinterpret_cast<float*>(sm);
    int*   sdst  = reinterpret_cast<int*>(sm + 33280);
    if (tid < 128) sdst[tid] = dst[rowBase + tid];

    #pragma unroll
    for (int nt = 0; nt < 4; nt++) {
        int n = warp_n * 32 + nt * 8 + (lane & 3) * 2;
        float2 bb = *reinterpret_cast<const float2*>(b2 + n);
        #pragma unroll
        for (int mt = 0; mt < 2; mt++) {
            #pragma unroll
            for (int half = 0; half < 2; half++) {
                int row_l = warp_m * 32 + mt * 16 + (lane >> 2) + half * 8;
                size_t off = (size_t)(rowBase + row_l) * 64 + n;
                float2 rr = *reinterpret_cast<const float2*>(einb + off);
                float vx = acc2[mt][nt][half * 2 + 0] + bb.x + rr.x;
                float vy = acc2[mt][nt][half * 2 + 1] + bb.y + rr.y;
                float2 o; o.x = vx; o.y = vy;
                *reinterpret_cast<float2*>(eoutb + off) = o;
                stage[row_l * 65 + n]     = vx;
                stage[row_l * 65 + n + 1] = vy;
            }
        }
    }
    __syncthreads();

    {
        int col = tid & 63;
        int seg = tid >> 6;
        int r0  = seg * 32;
        float sum = 0.f;
        int cur = sdst[r0];
        for (int r = r0; r < r0 + 32; r++) {
            int d  = sdst[r];
            float v = stage[r * 65 + col];
            if (d != cur) {
                atomicAdd(aggb + (size_t)cur * 64 + col, sum);
                sum = 0.f;
                cur = d;
            }
            sum += v;
        }
        atomicAdd(aggb + (size_t)cur * 64 + col, sum);
    }
}

// =====================================================================
//  Weight prep — single kernel
// =====================================================================
__device__ __forceinline__ void splitStore(float v, __nv_bfloat16* hi,
                                           __nv_bfloat16* lo, int i) {
    __nv_bfloat16 h = __float2bfloat16_rn(v);
    hi[i] = h;
    lo[i] = __float2bfloat16_rn(v - __bfloat162float(h));
}

#define T_PE1 (NLAYERS*576*HIDD)
#define T_WSD (NLAYERS*256*1024)
#define T_PE2 (NLAYERS*HIDD*EDGE_D)
#define T_PN1 (NLAYERS*320*HIDD)
#define T_PN2 (NLAYERS*HIDD*NODE_D)
#define T_DC1 (NODE_D*HIDD)
#define T_EN2 (HIDD*NODE_D)
#define T_DC2 (HIDD*80)
#define T_EM2 (EDGE_D*EDGE_D)
#define T_ALL (T_PE1+T_WSD+T_PE2+T_PN1+T_PN2+T_DC1+T_EN2+T_DC2+T_EM2+80+NMESH)

__global__ void prep_all(const float* __restrict__ pe_w1, const float* __restrict__ pe_w2,
                         const float* __restrict__ pn_w1, const float* __restrict__ pn_w2,
                         const float* __restrict__ dec_w1, const float* __restrict__ enc_w2,
                         const float* __restrict__ dec_w2, const float* __restrict__ dec_b2,
                         const float* __restrict__ eme_w2)
{
    int i = blockIdx.x * blockDim.x + threadIdx.x;
    if (i < T_PE1) { splitStore(pe_w1[i], g_pe1hi, g_pe1lo, i); return; }
    i -= T_PE1;
    if (i < T_WSD) {
        int l = i >> 18, rem = i & 262143;
        int r = rem >> 10, n = rem & 1023;
        int srow = (n < 512) ? (64 + r) : (320 + r);
        float v = pe_w1[(size_t)l * 576 * 512 + (size_t)srow * 512 + (n & 511)];
        splitStore(v, g_wsdhi, g_wsdlo, i);
        return;
    }
    i -= T_WSD;
    if (i < T_PE2) { splitStore(pe_w2[i], g_pe2hi, g_pe2lo, i); return; }
    i -= T_PE2;
    if (i < T_PN1) { splitStore(pn_w1[i], g_pn1hi, g_pn1lo, i); return; }
    i -= T_PN1;
    if (i < T_PN2) { splitStore(pn_w2[i], g_pn2hi, g_pn2lo, i); return; }
    i -= T_PN2;
    if (i < T_DC1) { splitStore(dec_w1[i], g_dc1hi, g_dc1lo, i); return; }
    i -= T_DC1;
    if (i < T_EN2) { splitStore(enc_w2[i], g_en2hi, g_en2lo, i); return; }
    i -= T_EN2;
    if (i < T_DC2) {
        int k = i / 80, n = i % 80;
        splitStore((n < 78) ? dec_w2[k * 78 + n] : 0.f, g_dc2hi, g_dc2lo, i);
        return;
    }
    i -= T_DC2;
    if (i < T_EM2) { splitStore(eme_w2[i], g_em2hi, g_em2lo, i); return; }
    i -= T_EM2;
    if (i < 80) { g_dcb2p[i] = (i < 78) ? dec_b2[i] : 0.f; return; }
    i -= 80;
    if (i < NMESH) g_cnt[i] = 0;
}

// =====================================================================
//  Edge counting sort (by dst)
// =====================================================================
__global__ void sort_hist(const int* __restrict__ dst) {
    int j = blockIdx.x * blockDim.x + threadIdx.x;
    if (j < NEDGE) atomicAdd(&g_cnt[dst[j]], 1);
}

__global__ void __launch_bounds__(1024) sort_scan() {
    __shared__ int part[1024];
    const int tid = threadIdx.x;
    const int PER = (NMESH + 1023) / 1024;
    int local[11];
    int s = 0;
    #pragma unroll
    for (int i = 0; i < PER; i++) {
        int b = tid * PER + i;
        int c = (b < NMESH) ? g_cnt[b] : 0;
        local[i] = s;
        s += c;
    }
    part[tid] = s;
    __syncthreads();
    for (int off = 1; off < 1024; off <<= 1) {
        int v = (tid >= off) ? part[tid - off] : 0;
        __syncthreads();
        part[tid] += v;
        __syncthreads();
    }
    int excl = (tid == 0) ? 0 : part[tid - 1];
    #pragma unroll
    for (int i = 0; i < PER; i++) {
        int b = tid * PER + i;
        if (b < NMESH) g_off[b] = excl + local[i];
    }
}

__global__ void sort_scatter(const int* __restrict__ src, const int* __restrict__ dst,
                             const float* __restrict__ redge) {
    int j = blockIdx.x * blockDim.x + threadIdx.x;
    if (j >= NEDGE) return;
    int d = dst[j];
    int pos = atomicAdd(&g_off[d], 1);
    g_srcS[pos] = src[j];
    g_dstS[pos] = d;
    float4 rv = reinterpret_cast<const float4*>(redge)[j];
    reinterpret_cast<float4*>(g_redgeS)[pos] = rv;
}

// =====================================================================
//  SIMT fp32 GEMM (encoder MLP1, embedder MLP1)
// =====================================================================
template<int BM, int BN, int BK, int TM, int TN>
__global__ void __launch_bounds__(256)
sgemm_bias(const float* __restrict__ A, int lda,
           const float* __restrict__ W,
           const float* __restrict__ bias,
           const float* res, float* C,
           int M, int N, int K, int doRelu)
{
    constexpr int GN      = TN / 4;
    constexpr int CSTRIDE = BN / GN;
    constexpr int NTC     = BN / TN;
    constexpr int THREADS = (BM / TM) * NTC;
    static_assert(THREADS == 256, "expect 256 threads");
    static_assert(BK == 16 && THREADS == BM * 2, "A loader mapping");

    __shared__ float As[BK][BM + 4];
    __shared__ float Bs[BK][BN];

    const int tid  = threadIdx.x;
    const int tcol = tid % NTC;
    const int trow = tid / NTC;
    const int rowBase = blockIdx.y * BM;
    const int colBase = blockIdx.x * BN;

    float acc[TM][TN];
    #pragma unroll
    for (int i = 0; i < TM; i++)
        #pragma unroll
        for (int j = 0; j < TN; j++) acc[i][j] = 0.f;

    const int am = tid >> 1;
    const int ah = (tid & 1) * 8;

    for (int k0 = 0; k0 < K; k0 += BK) {
        {
            const int gm = rowBase + am;
            const bool mok = (gm < M);
            const float* Arow = A + (size_t)gm * lda + (k0 + ah);
            #pragma unroll
            for (int i = 0; i < 8; i++) {
                int gk = k0 + ah + i;
                As[ah + i][am] = (mok && gk < K) ? Arow[i] : 0.f;
            }
        }
        #pragma unroll
        for (int it = 0; it < (BK * BN) / THREADS; it++) {
            int idx = tid + it * THREADS;
            int k = idx / BN, n = idx % BN;
            int gk = k0 + k, gn = colBase + n;
            Bs[k][n] = (gk < K && gn < N) ? W[(size_t)gk * N + gn] : 0.f;
        }
        __syncthreads();

        #pragma unroll
        for (int k = 0; k < BK; k++) {
            float ra[TM], rb[TN];
            #pragma unroll
            for (int i = 0; i < TM; i++) ra[i] = As[k][trow * TM + i];
            #pragma unroll
            for (int cg = 0; cg < GN; cg++)
                #pragma unroll
                for (int j = 0; j < 4; j++)
                    rb[cg * 4 + j] = Bs[k][cg * CSTRIDE + tcol * 4 + j];
            #pragma unroll
            for (int i = 0; i < TM; i++)
                #pragma unroll
                for (int j = 0; j < TN; j++)
                    acc[i][j] = fmaf(ra[i], rb[j], acc[i][j]);
        }
        __syncthreads();
    }

    #pragma unroll
    for (int i = 0; i < TM; i++) {
        int gm = rowBase + trow * TM + i;
        if (gm >= M) continue;
        #pragma unroll
        for (int cg = 0; cg < GN; cg++) {
            #pragma unroll
            for (int j = 0; j < 4; j++) {
                int gn = colBase + cg * CSTRIDE + tcol * 4 + j;
                if (gn >= N) continue;
                float v = acc[i][cg * 4 + j] + bias[gn];
                if (doRelu) v = fmaxf(v, 0.f);
                size_t off = (size_t)gm * N + gn;
                if (res) v += res[off];
                C[off] = v;
            }
        }
    }
}

// ---------------- builders ----------------
__global__ void build_encin(const float* __restrict__ xc, const float* __restrict__ xp,
                            const float* __restrict__ geo, const int* __restrict__ g2m,
                            float* __restrict__ out)
{
    int idx = blockIdx.x * blockDim.x + threadIdx.x;
    const int total = NBATCH * NMESH * ENC_LDA;
    if (idx >= total) return;
    int row = idx / ENC_LDA;
    int c   = idx - row * ENC_LDA;
    int b   = row / NMESH;
    int m   = row - b * NMESH;
    float v = 0.f;
    if (c < NV)            v = xc[((size_t)b * NGRID + g2m[m]) * NV + c];
    else if (c < 2 * NV)   v = xp[((size_t)b * NGRID + g2m[m]) * NV + (c - NV)];
    else if (c < ENC_IN)   v = geo[m * 7 + (c - 2 * NV)];
    out[idx] = v;
}

// ---------------- launcher ----------------
static inline dim3 gemm_grid(int M, int N, int BM, int BN) {
    return dim3((unsigned)((N + BN - 1) / BN), (unsigned)((M + BM - 1) / BM));
}

extern "C" void kernel_launch(void* const* d_in, const int* in_sizes, int n_in,
                              void* d_out, int out_size)
{
    const float* xc     = (const float*)d_in[0];
    const float* xp     = (const float*)d_in[1];
    const float* geo    = (const float*)d_in[2];
    const float* redge  = (const float*)d_in[3];
    const int*   eidx   = (const int*)  d_in[4];
    const int*   g2m    = (const int*)  d_in[5];
    const int*   m2g    = (const int*)  d_in[6];
    const float* enc_w1 = (const float*)d_in[7];
    const float* enc_b1 = (const float*)d_in[8];
    const float* enc_w2 = (const float*)d_in[9];
    const float* enc_b2 = (const float*)d_in[10];
    const float* eme_w1 = (const float*)d_in[11];
    const float* eme_b1 = (const float*)d_in[12];
    const float* eme_w2 = (const float*)d_in[13];
    const float* eme_b2 = (const float*)d_in[14];
    const float* pe_w1  = (const float*)d_in[15];
    const float* pe_b1  = (const float*)d_in[16];
    const float* pe_w2  = (const float*)d_in[17];
    const float* pe_b2  = (const float*)d_in[18];
    const float* pn_w1  = (const float*)d_in[19];
    const float* pn_b1  = (const float*)d_in[20];
    const float* pn_w2  = (const float*)d_in[21];
    const float* pn_b2  = (const float*)d_in[22];
    const float* dec_w1 = (const float*)d_in[23];
    const float* dec_b1 = (const float*)d_in[24];
    const float* dec_w2 = (const float*)d_in[25];
    const float* dec_b2 = (const float*)d_in[26];
    float* out = (float*)d_out;

    float *encin, *x, *e, *e0, *h, *agg, *xsd, *zeros, *dcb2p, *redgeS;
    int *srcS, *dstS;
    __nv_bfloat16 *pe1hi,*pe1lo,*wsdhi,*wsdlo,*pe2hi,*pe2lo,*pn1hi,*pn1lo,*pn2hi,*pn2lo;
    __nv_bfloat16 *dc1hi,*dc1lo,*dc2hi,*dc2lo,*en2hi,*en2lo,*em2hi,*em2lo;
    cudaGetSymbolAddress((void**)&encin, g_encin);
    cudaGetSymbolAddress((void**)&x,     g_x);
    cudaGetSymbolAddress((void**)&e,     g_e);
    cudaGetSymbolAddress((void**)&e0,    g_e0);
    cudaGetSymbolAddress((void**)&h,     g_h);
    cudaGetSymbolAddress((void**)&agg,   g_agg);
    cudaGetSymbolAddress((void**)&xsd,   g_xsd);
    cudaGetSymbolAddress((void**)&zeros, g_zeros);
    cudaGetSymbolAddress((void**)&dcb2p, g_dcb2p);
    cudaGetSymbolAddress((void**)&redgeS,g_redgeS);
    cudaGetSymbolAddress((void**)&srcS,  g_srcS);
    cudaGetSymbolAddress((void**)&dstS,  g_dstS);
    cudaGetSymbolAddress((void**)&pe1hi, g_pe1hi);
    cudaGetSymbolAddress((void**)&pe1lo, g_pe1lo);
    cudaGetSymbolAddress((void**)&wsdhi, g_wsdhi);
    cudaGetSymbolAddress((void**)&wsdlo, g_wsdlo);
    cudaGetSymbolAddress((void**)&pe2hi, g_pe2hi);
    cudaGetSymbolAddress((void**)&pe2lo, g_pe2lo);
    cudaGetSymbolAddress((void**)&pn1hi, g_pn1hi);
    cudaGetSymbolAddress((void**)&pn1lo, g_pn1lo);
    cudaGetSymbolAddress((void**)&pn2hi, g_pn2hi);
    cudaGetSymbolAddress((void**)&pn2lo, g_pn2lo);
    cudaGetSymbolAddress((void**)&dc1hi, g_dc1hi);
    cudaGetSymbolAddress((void**)&dc1lo, g_dc1lo);
    cudaGetSymbolAddress((void**)&dc2hi, g_dc2hi);
    cudaGetSymbolAddress((void**)&dc2lo, g_dc2lo);
    cudaGetSymbolAddress((void**)&en2hi, g_en2hi);
    cudaGetSymbolAddress((void**)&en2lo, g_en2lo);
    cudaGetSymbolAddress((void**)&em2hi, g_em2hi);
    cudaGetSymbolAddress((void**)&em2lo, g_em2lo);

    const int* src = eidx;
    const int* dst = eidx + NEDGE;

    constexpr int SM64N  = 2 * (2 * 128 * 72 * 2) + 2 * (2 * 64 * 72 * 2);  // 110592
    constexpr int SM80   = 2 * (2 * 128 * 72 * 2) + 2 * (2 * 64 * 88 * 2);  // 118784
    constexpr int SMFUSE = 110592;

    cudaFuncSetAttribute((const void*)mma_gemm<512,2,64,2,8,0,false,false,false>,
                         cudaFuncAttributeMaxDynamicSharedMemorySize, SM64N);
    cudaFuncSetAttribute((const void*)mma_gemm<512,2,64,2,8,0,false,true,false>,
                         cudaFuncAttributeMaxDynamicSharedMemorySize, SM64N);
    cudaFuncSetAttribute((const void*)mma_gemm<512,2,64,2,5,2,true,false,false>,
                         cudaFuncAttributeMaxDynamicSharedMemorySize, SM64N);
    cudaFuncSetAttribute((const void*)mma_gemm<512,2,64,2,4,4,true,false,false>,
                         cudaFuncAttributeMaxDynamicSharedMemorySize, SM64N);
    cudaFuncSetAttribute((const void*)mma_gemm<512,2,64,2,4,0,false,false,true>,
                         cudaFuncAttributeMaxDynamicSharedMemorySize, SM64N);
    cudaFuncSetAttribute((const void*)mma_gemm<512,2,64,2,1,0,false,false,false>,
                         cudaFuncAttributeMaxDynamicSharedMemorySize, SM64N);
    cudaFuncSetAttribute((const void*)mma_gemm<256,1,80,1,8,0,false,false,false>,
                         cudaFuncAttributeMaxDynamicSharedMemorySize, SM80);
    cudaFuncSetAttribute((const void*)fused_edge,
                         cudaFuncAttributeMaxDynamicSharedMemorySize, SMFUSE);

    // ---------- prep: weights + sort ----------
    prep_all<<<((int)T_ALL + 255) / 256, 256>>>(pe_w1, pe_w2, pn_w1, pn_w2,
                                                dec_w1, enc_w2, dec_w2, dec_b2, eme_w2);
    sort_hist<<<(NEDGE + 255) / 256, 256>>>(dst);
    sort_scan<<<1, 1024>>>();
    sort_scatter<<<(NEDGE + 255) / 256, 256>>>(src, dst, redge);

    // ---------- encoder ----------
    {
        int total = NBATCH * NMESH * ENC_LDA;
        build_encin<<<(total + 255) / 256, 256>>>(xc, xp, geo, g2m, encin);
    }
    sgemm_bias<128,128,16,8,8><<<gemm_grid(NBATCH*NMESH, HIDD, 128, 128), 256>>>(
        encin, ENC_LDA, enc_w1, enc_b1, nullptr, h, NBATCH*NMESH, HIDD, ENC_IN, 1);
    mma_gemm<512,2,64,2,8,0,false,false,false><<<dim3(4, (NBATCH*NMESH + 127)/128), 512, SM64N>>>(
        h, nullptr, nullptr, en2hi, en2lo, enc_b2, nullptr, x, nullptr,
        NBATCH*NMESH, NODE_D, NODE_D, NODE_D);

    // ---------- edge embedder (sorted edge space) ----------
    sgemm_bias<128,64,16,8,4><<<gemm_grid(NEDGE, EDGE_D, 128, 64), 256>>>(
        redgeS, 4, eme_w1, eme_b1, nullptr, h, NEDGE, EDGE_D, 4, 1);
    mma_gemm<512,2,64,2,1,0,false,false,false><<<dim3(1, NEDGE/128), 512, SM64N>>>(
        h, nullptr, nullptr, em2hi, em2lo, eme_b2, nullptr, e0, nullptr,
        NEDGE, EDGE_D, EDGE_D, EDGE_D);

    // ---------- GNN layers (both batches per launch) ----------
    const int MN = NBATCH * NMESH;   // 20484
    for (int l = 0; l < NLAYERS; l++) {
        const float* ein = (l == 0) ? e0 : e;
        size_t einStride = (l == 0) ? 0 : (size_t)NEDGE * EDGE_D;

        // xsd = x @ [Wsrc | Wdst]  (M=20484, K=256, N=1024); also zeroes agg
        mma_gemm<512,2,64,2,4,0,false,false,true><<<dim3(16, (MN+127)/128), 512, SM64N>>>(
            x, nullptr, nullptr,
            wsdhi + (size_t)l*256*1024, wsdlo + (size_t)l*256*1024,
            zeros, nullptr, xsd, agg, MN, 1024, 1024, 1024);

        // fused edge MLP for both batches (dst-sorted, 2 CTAs/SM)
        fused_edge<<<dim3(NEDGE/128, NBATCH), 256, SMFUSE>>>(
            ein, xsd, srcS, dstS,
            pe1hi + (size_t)l*576*HIDD, pe1lo + (size_t)l*576*HIDD,
            pe2hi + (size_t)l*HIDD*EDGE_D, pe2lo + (size_t)l*HIDD*EDGE_D,
            pe_b1 + (size_t)l*HIDD, pe_b2 + (size_t)l*EDGE_D,
            e, agg, einStride);

        // node MLP1: [x | agg] @ W1 + b, relu  (M=20484)
        mma_gemm<512,2,64,2,5,2,true,false,false><<<dim3(8, (MN+127)/128), 512, SM64N>>>(
            x, agg, nullptr,
            pn1hi + (size_t)l*320*HIDD, pn1lo + (size_t)l*320*HIDD,
            pn_b1 + (size_t)l*HIDD, nullptr, h, nullptr, MN, HIDD, HIDD, HIDD);
        // node MLP2: h @ W2 + b + x (in place, M=20484)
        mma_gemm<512,2,64,2,8,0,false,true,false><<<dim3(4, (MN+127)/128), 512, SM64N>>>(
            h, nullptr, nullptr,
            pn2hi + (size_t)l*HIDD*NODE_D, pn2lo + (size_t)l*HIDD*NODE_D,
            pn_b2 + (size_t)l*NODE_D, x, x, nullptr, MN, NODE_D, NODE_D, NODE_D);
    }

    // ---------- decoder ----------
    mma_gemm<512,2,64,2,4,4,true,false,false><<<dim3(8, (NBATCH*NGRID+127)/128), 512, SM64N>>>(
        x, nullptr, m2g,
        dc1hi, dc1lo, dec_b1, nullptr,
        h, nullptr, NBATCH*NGRID, HIDD, HIDD, HIDD);
    mma_gemm<256,1,80,1,8,0,false,false,false><<<dim3(1, (NBATCH*NGRID + 127)/128), 256, SM80>>>(
        h, nullptr, nullptr, dc2hi, dc2lo, dcb2p, nullptr, out, nullptr,
        NBATCH*NGRID, 80, 78, 78);
}

// round 15
// speedup vs baseline: 1.0167x; 1.0167x over previous
#include <cuda_runtime.h>
#include <cuda_bf16.h>
#include <cstdint>

// ---------------- problem constants ----------------
#define NLAT   181
#define NLON   360
#define NV     78
#define NGRID  (NLAT*NLON)      // 65160
#define NBATCH 2
#define NMESH  10242
#define NEDGE  163840
#define NODE_D 256
#define EDGE_D 64
#define HIDD   512
#define NLAYERS 16
#define ENC_IN  163
#define ENC_LDA 164

// ---------------- device scratch ----------------
__device__ float g_encin[(size_t)NBATCH*NMESH*ENC_LDA];
__device__ float g_x    [(size_t)NBATCH*NMESH*NODE_D];
__device__ float g_e    [(size_t)NBATCH*NEDGE*EDGE_D];
__device__ float g_e0   [(size_t)NEDGE*EDGE_D];
__device__ float g_h    [(size_t)NEDGE*HIDD];
__device__ float g_agg  [(size_t)NBATCH*NMESH*EDGE_D];
__device__ float g_xsd  [(size_t)NBATCH*NMESH*1024];
__device__ float g_zeros[1024];
__device__ float g_dcb2p[80];
// edge sort (dst-sorted order; edge state lives in sorted space forever)
__device__ int   g_cnt  [NMESH];
__device__ int   g_off  [NMESH];
__device__ int   g_srcS [NEDGE];
__device__ int   g_dstS [NEDGE];
__device__ float g_redgeS[(size_t)NEDGE*4];
// bf16 hi/lo split weights
__device__ __nv_bfloat16 g_pe1hi[(size_t)NLAYERS*576*HIDD];
__device__ __nv_bfloat16 g_pe1lo[(size_t)NLAYERS*576*HIDD];
__device__ __nv_bfloat16 g_wsdhi[(size_t)NLAYERS*256*1024];
__device__ __nv_bfloat16 g_wsdlo[(size_t)NLAYERS*256*1024];
__device__ __nv_bfloat16 g_pe2hi[(size_t)NLAYERS*HIDD*EDGE_D];
__device__ __nv_bfloat16 g_pe2lo[(size_t)NLAYERS*HIDD*EDGE_D];
__device__ __nv_bfloat16 g_pn1hi[(size_t)NLAYERS*320*HIDD];
__device__ __nv_bfloat16 g_pn1lo[(size_t)NLAYERS*320*HIDD];
__device__ __nv_bfloat16 g_pn2hi[(size_t)NLAYERS*HIDD*NODE_D];
__device__ __nv_bfloat16 g_pn2lo[(size_t)NLAYERS*HIDD*NODE_D];
__device__ __nv_bfloat16 g_dc1hi[(size_t)NODE_D*HIDD];
__device__ __nv_bfloat16 g_dc1lo[(size_t)NODE_D*HIDD];
__device__ __nv_bfloat16 g_dc2hi[(size_t)HIDD*80];
__device__ __nv_bfloat16 g_dc2lo[(size_t)HIDD*80];
__device__ __nv_bfloat16 g_en2hi[(size_t)HIDD*NODE_D];
__device__ __nv_bfloat16 g_en2lo[(size_t)HIDD*NODE_D];
__device__ __nv_bfloat16 g_em2hi[(size_t)EDGE_D*EDGE_D];
__device__ __nv_bfloat16 g_em2lo[(size_t)EDGE_D*EDGE_D];

// ---------------- asm helpers ----------------
__device__ __forceinline__ void ldsm_x4(uint32_t* r, uint32_t addr) {
    asm volatile("ldmatrix.sync.aligned.m8n8.x4.shared.b16 {%0,%1,%2,%3}, [%4];"
        : "=r"(r[0]), "=r"(r[1]), "=r"(r[2]), "=r"(r[3]) : "r"(addr));
}
__device__ __forceinline__ void ldsm_x4t(uint32_t* r, uint32_t addr) {
    asm volatile("ldmatrix.sync.aligned.m8n8.x4.trans.shared.b16 {%0,%1,%2,%3}, [%4];"
        : "=r"(r[0]), "=r"(r[1]), "=r"(r[2]), "=r"(r[3]) : "r"(addr));
}
__device__ __forceinline__ void mma16816(float* d, const uint32_t* a, const uint32_t* b) {
    asm volatile("mma.sync.aligned.m16n8k16.row.col.f32.bf16.bf16.f32 "
        "{%0,%1,%2,%3}, {%4,%5,%6,%7}, {%8,%9}, {%0,%1,%2,%3};"
        : "+f"(d[0]), "+f"(d[1]), "+f"(d[2]), "+f"(d[3])
        : "r"(a[0]), "r"(a[1]), "r"(a[2]), "r"(a[3]), "r"(b[0]), "r"(b[1]));
}
__device__ __forceinline__ uint32_t smem_u32(const void* p) {
    uint32_t a;
    asm("{ .reg .u64 t; cvta.to.shared.u64 t, %1; cvt.u32.u64 %0, t; }" : "=r"(a) : "l"(p));
    return a;
}
#define CP_ASYNC16(dst, src) \
    asm volatile("cp.async.cg.shared.global [%0], [%1], 16;" :: "r"(dst), "l"(src))
#define CP_COMMIT() asm volatile("cp.async.commit_group;" ::: "memory")
#define CP_WAIT0()  asm volatile("cp.async.wait_group 0;" ::: "memory")
#define STS_V2(addr, x, y) \
    asm volatile("st.shared.v2.u32 [%0], {%1,%2};" :: "r"(addr), "r"(x), "r"(y))
#define STS_U32(addr, x) \
    asm volatile("st.shared.u32 [%0], %1;" :: "r"(addr), "r"(x))

__device__ __forceinline__ void split4(float4 v, uint2& hh, uint2& ll) {
    __nv_bfloat16 h0 = __float2bfloat16_rn(v.x), h1 = __float2bfloat16_rn(v.y);
    __nv_bfloat16 h2 = __float2bfloat16_rn(v.z), h3 = __float2bfloat16_rn(v.w);
    __nv_bfloat16 g0 = __float2bfloat16_rn(v.x - __bfloat162float(h0));
    __nv_bfloat16 g1 = __float2bfloat16_rn(v.y - __bfloat162float(h1));
    __nv_bfloat16 g2 = __float2bfloat16_rn(v.z - __bfloat162float(h2));
    __nv_bfloat16 g3 = __float2bfloat16_rn(v.w - __bfloat162float(h3));
    hh.x = (uint32_t)__bfloat16_as_ushort(h0) | ((uint32_t)__bfloat16_as_ushort(h1) << 16);
    hh.y = (uint32_t)__bfloat16_as_ushort(h2) | ((uint32_t)__bfloat16_as_ushort(h3) << 16);
    ll.x = (uint32_t)__bfloat16_as_ushort(g0) | ((uint32_t)__bfloat16_as_ushort(g1) << 16);
    ll.y = (uint32_t)__bfloat16_as_ushort(g2) | ((uint32_t)__bfloat16_as_ushort(g3) << 16);
}
__device__ __forceinline__ void split2(float vx, float vy, uint32_t& hp, uint32_t& lp) {
    __nv_bfloat16 hx = __float2bfloat16_rn(vx), hy = __float2bfloat16_rn(vy);
    __nv_bfloat16 lx = __float2bfloat16_rn(vx - __bfloat162float(hx));
    __nv_bfloat16 ly = __float2bfloat16_rn(vy - __bfloat162float(hy));
    hp = (uint32_t)__bfloat16_as_ushort(hx) | ((uint32_t)__bfloat16_as_ushort(hy) << 16);
    lp = (uint32_t)__bfloat16_as_ushort(lx) | ((uint32_t)__bfloat16_as_ushort(ly) << 16);
}

// ---------------- A-gather modes ----------------
// MODE 0: plain A[M][K]
// MODE 2: [x(256)|agg(64)]
// MODE 4: gathered rows A[m2g[g%NGRID] + (g/NGRID)*NMESH][256]
template<int MODE, int AIT, int RPI>
__device__ __forceinline__ void prefA(float4 (&Ra)[AIT], int c, int rowBase, int M,
    const float* __restrict__ A, const float* __restrict__ aux,
    const int (&sI)[AIT], int tid, int K)
{
    const int f = tid & 15;
    #pragma unroll
    for (int it = 0; it < AIT; it++) {
        int gr = rowBase + it * RPI + (tid >> 4);
        if (gr < M) {
            const float* p;
            if (MODE == 0)      p = A + (size_t)gr * K + c * 64;
            else if (MODE == 2) p = (c < 4) ? A + (size_t)gr * 256 + c * 64
                                            : aux + (size_t)gr * 64;
            else                p = A + (size_t)sI[it] * 256 + c * 64;
            Ra[it] = reinterpret_cast<const float4*>(p)[f];
        } else {
            Ra[it] = make_float4(0.f, 0.f, 0.f, 0.f);
        }
    }
}

// =====================================================================
//  HMMA GEMM: C[M x Nclip (pitch Cpitch)] = [res+] relu?(gather(A)@W + bias)
//  256 threads, BN=64, MINB=2 -> 110.6 KB smem, 2 CTAs/SM (R13-proven shape:
//  8 warps/CTA, warp tile 32x32, 128-reg budget).
//  ZAGG: CTAs in column 0 also zero zbuf rows.
// =====================================================================
template<int THREADS, int MINB, int BN, int WARPS_N, int NC, int MODE,
         bool RELU, bool HAS_RES, bool ZAGG>
__global__ void __launch_bounds__(THREADS, MINB)
mma_gemm(const float* __restrict__ A, const float* __restrict__ aux,
         const int* __restrict__ idx1,
         const __nv_bfloat16* __restrict__ Bhi, const __nv_bfloat16* __restrict__ Blo,
         const float* __restrict__ bias, const float* res, float* C,
         float* zbuf, int M, int Nfull, int Cpitch, int Nclip)
{
    constexpr int K       = NC * 64;
    constexpr int NWARP   = THREADS / 32;
    constexpr int WARPS_M = NWARP / WARPS_N;
    constexpr int WTM     = 128 / WARPS_M;
    constexpr int WTN     = BN / WARPS_N;
    constexpr int MT      = WTM / 16;
    constexpr int NT      = WTN / 8;
    constexpr int ASTRIDE = 72;
    constexpr int APLANE  = 128 * ASTRIDE * 2;
    constexpr int ABUF    = 2 * APLANE;
    constexpr int BSTRIDE = BN + 8;
    constexpr int BPLANE  = 64 * BSTRIDE * 2;
    constexpr int BBUF    = 2 * BPLANE;
    constexpr int GRAN    = BN / 8;
    constexpr int BTOT    = 2 * 64 * GRAN;
    constexpr int AIT     = 2048 / THREADS;
    constexpr int RPI     = THREADS / 16;
    static_assert((BTOT % THREADS) == 0, "B loader divisibility");

    extern __shared__ char sm[];
    const uint32_t smA = smem_u32(sm);
    const uint32_t smB = smA + 2 * ABUF;

    const int tid    = threadIdx.x;
    const int lane   = tid & 31;
    const int wid    = tid >> 5;
    const int warp_n = wid % WARPS_N;
    const int warp_m = wid / WARPS_N;
    const int rowBase = blockIdx.y * 128;
    const int colBase = blockIdx.x * BN;

    if (ZAGG && blockIdx.x == 0) {
        #pragma unroll
        for (int it = 0; it < 2048 / THREADS; it++) {
            int i = tid + it * THREADS;
            int r = rowBase + (i >> 4);
            if (r < M)
                reinterpret_cast<float4*>(zbuf)[(size_t)r * 16 + (i & 15)] =
                    make_float4(0.f, 0.f, 0.f, 0.f);
        }
    }

    int sI[AIT];
    #pragma unroll
    for (int it = 0; it < AIT; it++) {
        int gr = rowBase + it * RPI + (tid >> 4);
        int g  = (gr < M) ? gr : 0;
        if (MODE == 4) {
            int b = g / NGRID;
            sI[it] = idx1[g - b * NGRID] + b * NMESH;
        } else {
            sI[it] = 0;
        }
    }

    float acc[MT][NT][4];
    #pragma unroll
    for (int i = 0; i < MT; i++)
        #pragma unroll
        for (int j = 0; j < NT; j++)
            #pragma unroll
            for (int q = 0; q < 4; q++) acc[i][j][q] = 0.f;

    float4 Ra[AIT];
    prefA<MODE, AIT, RPI>(Ra, 0, rowBase, M, A, aux, sI, tid, K);

    {
        #pragma unroll
        for (int it = 0; it < BTOT / THREADS; it++) {
            int i = it * THREADS + tid;
            int plane = i / (64 * GRAN);
            int rem   = i % (64 * GRAN);
            int k = rem / GRAN, g = rem % GRAN;
            const __nv_bfloat16* sp = (plane ? Blo : Bhi)
                + (size_t)k * Nfull + colBase + g * 8;
            CP_ASYNC16(smB + plane * BPLANE + (uint32_t)(k * BSTRIDE + g * 8) * 2, sp);
        }
        CP_COMMIT();
    }

    for (int c = 0; c < NC; c++) {
        const int buf = c & 1;
        #pragma unroll
        for (int it = 0; it < AIT; it++) {
            int r = it * RPI + (tid >> 4);
            int f = tid & 15;
            uint2 hh, ll;
            split4(Ra[it], hh, ll);
            uint32_t off = smA + buf * ABUF + (uint32_t)(r * ASTRIDE + f * 4) * 2;
            STS_V2(off, hh.x, hh.y);
            STS_V2(off + APLANE, ll.x, ll.y);
        }
        if (c + 1 < NC) prefA<MODE, AIT, RPI>(Ra, c + 1, rowBase, M, A, aux, sI, tid, K);
        CP_WAIT0();
        __syncthreads();
        if (c + 1 < NC) {
            #pragma unroll
            for (int it = 0; it < BTOT / THREADS; it++) {
                int i = it * THREADS + tid;
                int plane = i / (64 * GRAN);
                int rem   = i % (64 * GRAN);
                int k = rem / GRAN, g = rem % GRAN;
                const __nv_bfloat16* sp = (plane ? Blo : Bhi)
                    + (size_t)(c + 1) * 64 * Nfull + (size_t)k * Nfull + colBase + g * 8;
                CP_ASYNC16(smB + (1 - buf) * BBUF + plane * BPLANE
                           + (uint32_t)(k * BSTRIDE + g * 8) * 2, sp);
            }
            CP_COMMIT();
        }

        #pragma unroll
        for (int ks = 0; ks < 4; ks++) {
            uint32_t Ah[MT][4], Al[MT][4];
            #pragma unroll
            for (int mt = 0; mt < MT; mt++) {
                uint32_t addr = smA + buf * ABUF
                    + (uint32_t)((warp_m * WTM + mt * 16 + (lane & 15)) * ASTRIDE
                                 + ks * 16 + (lane >> 4) * 8) * 2;
                ldsm_x4(Ah[mt], addr);
                ldsm_x4(Al[mt], addr + APLANE);
            }
            uint32_t Bh[(NT + 1) / 2][4], Bl[(NT + 1) / 2][4];
            #pragma unroll
            for (int np = 0; np < NT / 2; np++) {
                uint32_t addr = smB + buf * BBUF
                    + (uint32_t)((ks * 16 + (lane & 15)) * BSTRIDE
                                 + warp_n * WTN + np * 16 + (lane >> 4) * 8) * 2;
                ldsm_x4t(Bh[np], addr);
                ldsm_x4t(Bl[np], addr + BPLANE);
            }
            #pragma unroll
            for (int mt = 0; mt < MT; mt++)
                #pragma unroll
                for (int nt = 0; nt < NT; nt++) {
                    const uint32_t* bh = &Bh[nt >> 1][(nt & 1) * 2];
                    const uint32_t* bl = &Bl[nt >> 1][(nt & 1) * 2];
                    mma16816(acc[mt][nt], Ah[mt], bh);
                    mma16816(acc[mt][nt], Ah[mt], bl);
                    mma16816(acc[mt][nt], Al[mt], bh);
                }
        }
    }

    #pragma unroll
    for (int nt = 0; nt < NT; nt++) {
        int n = colBase + warp_n * WTN + nt * 8 + (lane & 3) * 2;
        if (n >= Nclip) continue;
        float2 bb = *reinterpret_cast<const float2*>(bias + n);
        #pragma unroll
        for (int mt = 0; mt < MT; mt++) {
            #pragma unroll
            for (int half = 0; half < 2; half++) {
                int row = rowBase + warp_m * WTM + mt * 16 + (lane >> 2) + half * 8;
                if (row < M) {
                    float vx = acc[mt][nt][half * 2 + 0] + bb.x;
                    float vy = acc[mt][nt][half * 2 + 1] + bb.y;
                    size_t off = (size_t)row * Cpitch + n;
                    if (HAS_RES) {
                        float2 rr = *reinterpret_cast<const float2*>(res + off);
                        vx += rr.x; vy += rr.y;
                    }
                    if (RELU) { vx = fmaxf(vx, 0.f); vy = fmaxf(vy, 0.f); }
                    float2 o; o.x = vx; o.y = vy;
                    *reinterpret_cast<float2*>(C + off) = o;
                }
            }
        }
    }
}

// =====================================================================
//  Fused edge layer (batched via blockIdx.y, edges dst-sorted):
//  256 threads / 8 warps, 110.6 KB smem -> 2 CTAs/SM.
// =====================================================================
__global__ void __launch_bounds__(256, 2)
fused_edge(const float* __restrict__ ein,
           const float* __restrict__ xsd,
           const int* __restrict__ src, const int* __restrict__ dst,
           const __nv_bfloat16* __restrict__ W1hi, const __nv_bfloat16* __restrict__ W1lo,
           const __nv_bfloat16* __restrict__ W2hi, const __nv_bfloat16* __restrict__ W2lo,
           const float* __restrict__ b1, const float* __restrict__ b2,
           float* __restrict__ eout, float* __restrict__ agg,
           size_t einBatchStride)
{
    constexpr int A_STR  = 72;
    constexpr int A_PL   = 128 * A_STR * 2;
    constexpr int OFF_A  = 0;
    constexpr int B1_STR = 72;
    constexpr int B1_PL  = 64 * B1_STR * 2;
    constexpr int OFF_B1 = 2 * A_PL;
    constexpr int H_STR  = 72;
    constexpr int H_PL   = 128 * H_STR * 2;
    constexpr int OFF_H  = OFF_B1 + 2 * B1_PL;
    constexpr int B2_STR = 72;
    constexpr int B2_PL  = 64 * B2_STR * 2;
    constexpr int OFF_B2 = OFF_H + 2 * H_PL;   // total 110592

    extern __shared__ char sm[];
    const uint32_t base = smem_u32(sm);

    const int tid  = threadIdx.x;
    const int lane = tid & 31;
    const int wid  = tid >> 5;
    const int warp_m = wid >> 1;
    const int warp_n = wid & 1;
    const int rowBase = blockIdx.x * 128;
    const int batch   = blockIdx.y;

    const float* einb = ein + (size_t)batch * einBatchStride;
    const float* xsdb = xsd + (size_t)batch * NMESH * 1024;
    float* eoutb = eout + (size_t)batch * NEDGE * EDGE_D;
    float* aggb  = agg  + (size_t)batch * NMESH * EDGE_D;

    int sidx[2][2], didx[2][2];
    #pragma unroll
    for (int mt = 0; mt < 2; mt++)
        #pragma unroll
        for (int half = 0; half < 2; half++) {
            int g = rowBase + warp_m * 32 + mt * 16 + (lane >> 2) + half * 8;
            sidx[mt][half] = src[g];
            didx[mt][half] = dst[g];
        }

    {
        const float4* E4 = reinterpret_cast<const float4*>(einb + (size_t)rowBase * 64);
        #pragma unroll
        for (int it = 0; it < 8; it++) {
            int i = tid + it * 256;
            int r = i >> 4, f = i & 15;
            float4 v = E4[r * 16 + f];
            uint2 hh, ll;
            split4(v, hh, ll);
            uint32_t off = base + OFF_A + (uint32_t)(r * A_STR + f * 4) * 2;
            STS_V2(off, hh.x, hh.y);
            STS_V2(off + A_PL, ll.x, ll.y);
        }
    }

    float acc2[2][4][4];
    #pragma unroll
    for (int i = 0; i < 2; i++)
        #pragma unroll
        for (int j = 0; j < 4; j++)
            #pragma unroll
            for (int q = 0; q < 4; q++) acc2[i][j][q] = 0.f;

    for (int nc = 0; nc < 8; nc++) {
        __syncthreads();
        #pragma unroll
        for (int it = 0; it < 4; it++) {
            int i = tid + it * 256;
            int plane = i >> 9;
            int rem = i & 511;
            int k = rem >> 3, g = rem & 7;
            const __nv_bfloat16* sp = (plane ? W1lo : W1hi)
                + (size_t)k * 512 + nc * 64 + g * 8;
            CP_ASYNC16(base + OFF_B1 + plane * B1_PL + (uint32_t)(k * B1_STR + g * 8) * 2, sp);
        }
        #pragma unroll
        for (int it = 0; it < 4; it++) {
            int i = tid + it * 256;
            int plane = i >> 9;
            int rem = i & 511;
            int k = rem >> 3, g = rem & 7;
            const __nv_bfloat16* sp = (plane ? W2lo : W2hi)
                + (size_t)(nc * 64 + k) * 64 + g * 8;
            CP_ASYNC16(base + OFF_B2 + plane * B2_PL + (uint32_t)(k * B2_STR + g * 8) * 2, sp);
        }
        CP_COMMIT();
        CP_WAIT0();
        __syncthreads();

        float acc1[2][4][4];
        #pragma unroll
        for (int i = 0; i < 2; i++)
            #pragma unroll
            for (int j = 0; j < 4; j++)
                #pragma unroll
                for (int q = 0; q < 4; q++) acc1[i][j][q] = 0.f;

        #pragma unroll
        for (int ks = 0; ks < 4; ks++) {
            uint32_t Ah[2][4], Al[2][4];
            #pragma unroll
            for (int mt = 0; mt < 2; mt++) {
                uint32_t addr = base + OFF_A
                    + (uint32_t)((warp_m * 32 + mt * 16 + (lane & 15)) * A_STR
                                 + ks * 16 + (lane >> 4) * 8) * 2;
                ldsm_x4(Ah[mt], addr);
                ldsm_x4(Al[mt], addr + A_PL);
            }
            uint32_t Bh[2][4], Bl[2][4];
            #pragma unroll
            for (int np = 0; np < 2; np++) {
                uint32_t addr = base + OFF_B1
                    + (uint32_t)((ks * 16 + (lane & 15)) * B1_STR
                                 + warp_n * 32 + np * 16 + (lane >> 4) * 8) * 2;
                ldsm_x4t(Bh[np], addr);
                ldsm_x4t(Bl[np], addr + B1_PL);
            }
            #pragma unroll
            for (int mt = 0; mt < 2; mt++)
                #pragma unroll
                for (int nt = 0; nt < 4; nt++) {
                    const uint32_t* bh = &Bh[nt >> 1][(nt & 1) * 2];
                    const uint32_t* bl = &Bl[nt >> 1][(nt & 1) * 2];
                    mma16816(acc1[mt][nt], Ah[mt], bh);
                    mma16816(acc1[mt][nt], Ah[mt], bl);
                    mma16816(acc1[mt][nt], Al[mt], bh);
                }
        }

        #pragma unroll
        for (int nt = 0; nt < 4; nt++) {
            int col  = warp_n * 32 + nt * 8 + (lane & 3) * 2;
            int gcol = nc * 64 + col;
            float2 bb = *reinterpret_cast<const float2*>(b1 + gcol);
            #pragma unroll
            for (int mt = 0; mt < 2; mt++) {
                #pragma unroll
                for (int half = 0; half < 2; half++) {
                    int row_l = warp_m * 32 + mt * 16 + (lane >> 2) + half * 8;
                    float2 sv = *reinterpret_cast<const float2*>(
                        xsdb + (size_t)sidx[mt][half] * 1024 + gcol);
                    float2 dv = *reinterpret_cast<const float2*>(
                        xsdb + (size_t)didx[mt][half] * 1024 + 512 + gcol);
                    float vx = fmaxf(acc1[mt][nt][half * 2 + 0] + bb.x + sv.x + dv.x, 0.f);
                    float vy = fmaxf(acc1[mt][nt][half * 2 + 1] + bb.y + sv.y + dv.y, 0.f);
                    uint32_t hp, lp;
                    split2(vx, vy, hp, lp);
                    uint32_t off = base + OFF_H + (uint32_t)(row_l * H_STR + col) * 2;
                    STS_U32(off, hp);
                    STS_U32(off + H_PL, lp);
                }
            }
        }
        __syncthreads();

        #pragma unroll
        for (int ks = 0; ks < 4; ks++) {
            uint32_t Ah[2][4], Al[2][4];
            #pragma unroll
            for (int mt = 0; mt < 2; mt++) {
                uint32_t addr = base + OFF_H
                    + (uint32_t)((warp_m * 32 + mt * 16 + (lane & 15)) * H_STR
                                 + ks * 16 + (lane >> 4) * 8) * 2;
                ldsm_x4(Ah[mt], addr);
                ldsm_x4(Al[mt], addr + H_PL);
            }
            uint32_t Bh[2][4], Bl[2][4];
            #pragma unroll
            for (int np = 0; np < 2; np++) {
                uint32_t addr = base + OFF_B2
                    + (uint32_t)((ks * 16 + (lane & 15)) * B2_STR
                                 + warp_n * 32 + np * 16 + (lane >> 4) * 8) * 2;
                ldsm_x4t(Bh[np], addr);
                ldsm_x4t(Bl[np], addr + B2_PL);
            }
            #pragma unroll
            for (int mt = 0; mt < 2; mt++)
                #pragma unroll
                for (int nt = 0; nt < 4; nt++) {
                    const uint32_t* bh = &Bh[nt >> 1][(nt & 1) * 2];
                    const uint32_t* bl = &Bl[nt >> 1][(nt & 1) * 2];
                    mma16816(acc2[mt][nt], Ah[mt], bh);
                    mma16816(acc2[mt][nt], Ah[mt], bl);
                    mma16816(acc2[mt][nt], Al[mt], bh);
                }
        }
    }

    __syncthreads();
    float* stage = reinterpret_cast<float*>(sm);
    int*   sdst  = reinterpret_cast<int*>(sm + 33280);
    if (tid < 128) sdst[tid] = dst[rowBase + tid];

    #pragma unroll
    for (int nt = 0; nt < 4; nt++) {
        int n = warp_n * 32 + nt * 8 + (lane & 3) * 2;
        float2 bb = *reinterpret_cast<const float2*>(b2 + n);
        #pragma unroll
        for (int mt = 0; mt < 2; mt++) {
            #pragma unroll
            for (int half = 0; half < 2; half++) {
                int row_l = warp_m * 32 + mt * 16 + (lane >> 2) + half * 8;
                size_t off = (size_t)(rowBase + row_l) * 64 + n;
                float2 rr = *reinterpret_cast<const float2*>(einb + off);
                float vx = acc2[mt][nt][half * 2 + 0] + bb.x + rr.x;
                float vy = acc2[mt][nt][half * 2 + 1] + bb.y + rr.y;
                float2 o; o.x = vx; o.y = vy;
                *reinterpret_cast<float2*>(eoutb + off) = o;
                stage[row_l * 65 + n]     = vx;
                stage[row_l * 65 + n + 1] = vy;
            }
        }
    }
    __syncthreads();

    {
        int col = tid & 63;
        int seg = tid >> 6;
        int r0  = seg * 32;
        float sum = 0.f;
        int cur = sdst[r0];
        for (int r = r0; r < r0 + 32; r++) {
            int d  = sdst[r];
            float v = stage[r * 65 + col];
            if (d != cur) {
                atomicAdd(aggb + (size_t)cur * 64 + col, sum);
                sum = 0.f;
                cur = d;
            }
            sum += v;
        }
        atomicAdd(aggb + (size_t)cur * 64 + col, sum);
    }
}

// =====================================================================
//  Weight prep — single kernel
// =====================================================================
__device__ __forceinline__ void splitStore(float v, __nv_bfloat16* hi,
                                           __nv_bfloat16* lo, int i) {
    __nv_bfloat16 h = __float2bfloat16_rn(v);
    hi[i] = h;
    lo[i] = __float2bfloat16_rn(v - __bfloat162float(h));
}

#define T_PE1 (NLAYERS*576*HIDD)
#define T_WSD (NLAYERS*256*1024)
#define T_PE2 (NLAYERS*HIDD*EDGE_D)
#define T_PN1 (NLAYERS*320*HIDD)
#define T_PN2 (NLAYERS*HIDD*NODE_D)
#define T_DC1 (NODE_D*HIDD)
#define T_EN2 (HIDD*NODE_D)
#define T_DC2 (HIDD*80)
#define T_EM2 (EDGE_D*EDGE_D)
#define T_ALL (T_PE1+T_WSD+T_PE2+T_PN1+T_PN2+T_DC1+T_EN2+T_DC2+T_EM2+80+NMESH)

__global__ void prep_all(const float* __restrict__ pe_w1, const float* __restrict__ pe_w2,
                         const float* __restrict__ pn_w1, const float* __restrict__ pn_w2,
                         const float* __restrict__ dec_w1, const float* __restrict__ enc_w2,
                         const float* __restrict__ dec_w2, const float* __restrict__ dec_b2,
                         const float* __restrict__ eme_w2)
{
    int i = blockIdx.x * blockDim.x + threadIdx.x;
    if (i < T_PE1) { splitStore(pe_w1[i], g_pe1hi, g_pe1lo, i); return; }
    i -= T_PE1;
    if (i < T_WSD) {
        int l = i >> 18, rem = i & 262143;
        int r = rem >> 10, n = rem & 1023;
        int srow = (n < 512) ? (64 + r) : (320 + r);
        float v = pe_w1[(size_t)l * 576 * 512 + (size_t)srow * 512 + (n & 511)];
        splitStore(v, g_wsdhi, g_wsdlo, i);
        return;
    }
    i -= T_WSD;
    if (i < T_PE2) { splitStore(pe_w2[i], g_pe2hi, g_pe2lo, i); return; }
    i -= T_PE2;
    if (i < T_PN1) { splitStore(pn_w1[i], g_pn1hi, g_pn1lo, i); return; }
    i -= T_PN1;
    if (i < T_PN2) { splitStore(pn_w2[i], g_pn2hi, g_pn2lo, i); return; }
    i -= T_PN2;
    if (i < T_DC1) { splitStore(dec_w1[i], g_dc1hi, g_dc1lo, i); return; }
    i -= T_DC1;
    if (i < T_EN2) { splitStore(enc_w2[i], g_en2hi, g_en2lo, i); return; }
    i -= T_EN2;
    if (i < T_DC2) {
        int k = i / 80, n = i % 80;
        splitStore((n < 78) ? dec_w2[k * 78 + n] : 0.f, g_dc2hi, g_dc2lo, i);
        return;
    }
    i -= T_DC2;
    if (i < T_EM2) { splitStore(eme_w2[i], g_em2hi, g_em2lo, i); return; }
    i -= T_EM2;
    if (i < 80) { g_dcb2p[i] = (i < 78) ? dec_b2[i] : 0.f; return; }
    i -= 80;
    if (i < NMESH) g_cnt[i] = 0;
}

// =====================================================================
//  Edge counting sort (by dst)
// =====================================================================
__global__ void sort_hist(const int* __restrict__ dst) {
    int j = blockIdx.x * blockDim.x + threadIdx.x;
    if (j < NEDGE) atomicAdd(&g_cnt[dst[j]], 1);
}

__global__ void __launch_bounds__(1024) sort_scan() {
    __shared__ int part[1024];
    const int tid = threadIdx.x;
    const int PER = (NMESH + 1023) / 1024;
    int local[11];
    int s = 0;
    #pragma unroll
    for (int i = 0; i < PER; i++) {
        int b = tid * PER + i;
        int c = (b < NMESH) ? g_cnt[b] : 0;
        local[i] = s;
        s += c;
    }
    part[tid] = s;
    __syncthreads();
    for (int off = 1; off < 1024; off <<= 1) {
        int v = (tid >= off) ? part[tid - off] : 0;
        __syncthreads();
        part[tid] += v;
        __syncthreads();
    }
    int excl = (tid == 0) ? 0 : part[tid - 1];
    #pragma unroll
    for (int i = 0; i < PER; i++) {
        int b = tid * PER + i;
        if (b < NMESH) g_off[b] = excl + local[i];
    }
}

__global__ void sort_scatter(const int* __restrict__ src, const int* __restrict__ dst,
                             const float* __restrict__ redge) {
    int j = blockIdx.x * blockDim.x + threadIdx.x;
    if (j >= NEDGE) return;
    int d = dst[j];
    int pos = atomicAdd(&g_off[d], 1);
    g_srcS[pos] = src[j];
    g_dstS[pos] = d;
    float4 rv = reinterpret_cast<const float4*>(redge)[j];
    reinterpret_cast<float4*>(g_redgeS)[pos] = rv;
}

// =====================================================================
//  SIMT fp32 GEMM (encoder MLP1, embedder MLP1)
// =====================================================================
template<int BM, int BN, int BK, int TM, int TN>
__global__ void __launch_bounds__(256)
sgemm_bias(const float* __restrict__ A, int lda,
           const float* __restrict__ W,
           const float* __restrict__ bias,
           const float* res, float* C,
           int M, int N, int K, int doRelu)
{
    constexpr int GN      = TN / 4;
    constexpr int CSTRIDE = BN / GN;
    constexpr int NTC     = BN / TN;
    constexpr int THREADS = (BM / TM) * NTC;
    static_assert(THREADS == 256, "expect 256 threads");
    static_assert(BK == 16 && THREADS == BM * 2, "A loader mapping");

    __shared__ float As[BK][BM + 4];
    __shared__ float Bs[BK][BN];

    const int tid  = threadIdx.x;
    const int tcol = tid % NTC;
    const int trow = tid / NTC;
    const int rowBase = blockIdx.y * BM;
    const int colBase = blockIdx.x * BN;

    float acc[TM][TN];
    #pragma unroll
    for (int i = 0; i < TM; i++)
        #pragma unroll
        for (int j = 0; j < TN; j++) acc[i][j] = 0.f;

    const int am = tid >> 1;
    const int ah = (tid & 1) * 8;

    for (int k0 = 0; k0 < K; k0 += BK) {
        {
            const int gm = rowBase + am;
            const bool mok = (gm < M);
            const float* Arow = A + (size_t)gm * lda + (k0 + ah);
            #pragma unroll
            for (int i = 0; i < 8; i++) {
                int gk = k0 + ah + i;
                As[ah + i][am] = (mok && gk < K) ? Arow[i] : 0.f;
            }
        }
        #pragma unroll
        for (int it = 0; it < (BK * BN) / THREADS; it++) {
            int idx = tid + it * THREADS;
            int k = idx / BN, n = idx % BN;
            int gk = k0 + k, gn = colBase + n;
            Bs[k][n] = (gk < K && gn < N) ? W[(size_t)gk * N + gn] : 0.f;
        }
        __syncthreads();

        #pragma unroll
        for (int k = 0; k < BK; k++) {
            float ra[TM], rb[TN];
            #pragma unroll
            for (int i = 0; i < TM; i++) ra[i] = As[k][trow * TM + i];
            #pragma unroll
            for (int cg = 0; cg < GN; cg++)
                #pragma unroll
                for (int j = 0; j < 4; j++)
                    rb[cg * 4 + j] = Bs[k][cg * CSTRIDE + tcol * 4 + j];
            #pragma unroll
            for (int i = 0; i < TM; i++)
                #pragma unroll
                for (int j = 0; j < TN; j++)
                    acc[i][j] = fmaf(ra[i], rb[j], acc[i][j]);
        }
        __syncthreads();
    }

    #pragma unroll
    for (int i = 0; i < TM; i++) {
        int gm = rowBase + trow * TM + i;
        if (gm >= M) continue;
        #pragma unroll
        for (int cg = 0; cg < GN; cg++) {
            #pragma unroll
            for (int j = 0; j < 4; j++) {
                int gn = colBase + cg * CSTRIDE + tcol * 4 + j;
                if (gn >= N) continue;
                float v = acc[i][cg * 4 + j] + bias[gn];
                if (doRelu) v = fmaxf(v, 0.f);
                size_t off = (size_t)gm * N + gn;
                if (res) v += res[off];
                C[off] = v;
            }
        }
    }
}

// ---------------- builders ----------------
__global__ void build_encin(const float* __restrict__ xc, const float* __restrict__ xp,
                            const float* __restrict__ geo, const int* __restrict__ g2m,
                            float* __restrict__ out)
{
    int idx = blockIdx.x * blockDim.x + threadIdx.x;
    const int total = NBATCH * NMESH * ENC_LDA;
    if (idx >= total) return;
    int row = idx / ENC_LDA;
    int c   = idx - row * ENC_LDA;
    int b   = row / NMESH;
    int m   = row - b * NMESH;
    float v = 0.f;
    if (c < NV)            v = xc[((size_t)b * NGRID + g2m[m]) * NV + c];
    else if (c < 2 * NV)   v = xp[((size_t)b * NGRID + g2m[m]) * NV + (c - NV)];
    else if (c < ENC_IN)   v = geo[m * 7 + (c - 2 * NV)];
    out[idx] = v;
}

// ---------------- launcher ----------------
static inline dim3 gemm_grid(int M, int N, int BM, int BN) {
    return dim3((unsigned)((N + BN - 1) / BN), (unsigned)((M + BM - 1) / BM));
}

extern "C" void kernel_launch(void* const* d_in, const int* in_sizes, int n_in,
                              void* d_out, int out_size)
{
    const float* xc     = (const float*)d_in[0];
    const float* xp     = (const float*)d_in[1];
    const float* geo    = (const float*)d_in[2];
    const float* redge  = (const float*)d_in[3];
    const int*   eidx   = (const int*)  d_in[4];
    const int*   g2m    = (const int*)  d_in[5];
    const int*   m2g    = (const int*)  d_in[6];
    const float* enc_w1 = (const float*)d_in[7];
    const float* enc_b1 = (const float*)d_in[8];
    const float* enc_w2 = (const float*)d_in[9];
    const float* enc_b2 = (const float*)d_in[10];
    const float* eme_w1 = (const float*)d_in[11];
    const float* eme_b1 = (const float*)d_in[12];
    const float* eme_w2 = (const float*)d_in[13];
    const float* eme_b2 = (const float*)d_in[14];
    const float* pe_w1  = (const float*)d_in[15];
    const float* pe_b1  = (const float*)d_in[16];
    const float* pe_w2  = (const float*)d_in[17];
    const float* pe_b2  = (const float*)d_in[18];
    const float* pn_w1  = (const float*)d_in[19];
    const float* pn_b1  = (const float*)d_in[20];
    const float* pn_w2  = (const float*)d_in[21];
    const float* pn_b2  = (const float*)d_in[22];
    const float* dec_w1 = (const float*)d_in[23];
    const float* dec_b1 = (const float*)d_in[24];
    const float* dec_w2 = (const float*)d_in[25];
    const float* dec_b2 = (const float*)d_in[26];
    float* out = (float*)d_out;

    float *encin, *x, *e, *e0, *h, *agg, *xsd, *zeros, *dcb2p, *redgeS;
    int *srcS, *dstS;
    __nv_bfloat16 *pe1hi,*pe1lo,*wsdhi,*wsdlo,*pe2hi,*pe2lo,*pn1hi,*pn1lo,*pn2hi,*pn2lo;
    __nv_bfloat16 *dc1hi,*dc1lo,*dc2hi,*dc2lo,*en2hi,*en2lo,*em2hi,*em2lo;
    cudaGetSymbolAddress((void**)&encin, g_encin);
    cudaGetSymbolAddress((void**)&x,     g_x);
    cudaGetSymbolAddress((void**)&e,     g_e);
    cudaGetSymbolAddress((void**)&e0,    g_e0);
    cudaGetSymbolAddress((void**)&h,     g_h);
    cudaGetSymbolAddress((void**)&agg,   g_agg);
    cudaGetSymbolAddress((void**)&xsd,   g_xsd);
    cudaGetSymbolAddress((void**)&zeros, g_zeros);
    cudaGetSymbolAddress((void**)&dcb2p, g_dcb2p);
    cudaGetSymbolAddress((void**)&redgeS,g_redgeS);
    cudaGetSymbolAddress((void**)&srcS,  g_srcS);
    cudaGetSymbolAddress((void**)&dstS,  g_dstS);
    cudaGetSymbolAddress((void**)&pe1hi, g_pe1hi);
    cudaGetSymbolAddress((void**)&pe1lo, g_pe1lo);
    cudaGetSymbolAddress((void**)&wsdhi, g_wsdhi);
    cudaGetSymbolAddress((void**)&wsdlo, g_wsdlo);
    cudaGetSymbolAddress((void**)&pe2hi, g_pe2hi);
    cudaGetSymbolAddress((void**)&pe2lo, g_pe2lo);
    cudaGetSymbolAddress((void**)&pn1hi, g_pn1hi);
    cudaGetSymbolAddress((void**)&pn1lo, g_pn1lo);
    cudaGetSymbolAddress((void**)&pn2hi, g_pn2hi);
    cudaGetSymbolAddress((void**)&pn2lo, g_pn2lo);
    cudaGetSymbolAddress((void**)&dc1hi, g_dc1hi);
    cudaGetSymbolAddress((void**)&dc1lo, g_dc1lo);
    cudaGetSymbolAddress((void**)&dc2hi, g_dc2hi);
    cudaGetSymbolAddress((void**)&dc2lo, g_dc2lo);
    cudaGetSymbolAddress((void**)&en2hi, g_en2hi);
    cudaGetSymbolAddress((void**)&en2lo, g_en2lo);
    cudaGetSymbolAddress((void**)&em2hi, g_em2hi);
    cudaGetSymbolAddress((void**)&em2lo, g_em2lo);

    const int* src = eidx;
    const int* dst = eidx + NEDGE;

    constexpr int SM64N  = 2 * (2 * 128 * 72 * 2) + 2 * (2 * 64 * 72 * 2);  // 110592
    constexpr int SM80   = 2 * (2 * 128 * 72 * 2) + 2 * (2 * 64 * 88 * 2);  // 118784
    constexpr int SMFUSE = 110592;

    cudaFuncSetAttribute((const void*)mma_gemm<256,2,64,2,8,0,false,false,false>,
                         cudaFuncAttributeMaxDynamicSharedMemorySize, SM64N);
    cudaFuncSetAttribute((const void*)mma_gemm<256,2,64,2,8,0,false,true,false>,
                         cudaFuncAttributeMaxDynamicSharedMemorySize, SM64N);
    cudaFuncSetAttribute((const void*)mma_gemm<256,2,64,2,5,2,true,false,false>,
                         cudaFuncAttributeMaxDynamicSharedMemorySize, SM64N);
    cudaFuncSetAttribute((const void*)mma_gemm<256,2,64,2,4,4,true,false,false>,
                         cudaFuncAttributeMaxDynamicSharedMemorySize, SM64N);
    cudaFuncSetAttribute((const void*)mma_gemm<256,2,64,2,4,0,false,false,true>,
                         cudaFuncAttributeMaxDynamicSharedMemorySize, SM64N);
    cudaFuncSetAttribute((const void*)mma_gemm<256,2,64,2,1,0,false,false,false>,
                         cudaFuncAttributeMaxDynamicSharedMemorySize, SM64N);
    cudaFuncSetAttribute((const void*)mma_gemm<256,1,80,1,8,0,false,false,false>,
                         cudaFuncAttributeMaxDynamicSharedMemorySize, SM80);
    cudaFuncSetAttribute((const void*)fused_edge,
                         cudaFuncAttributeMaxDynamicSharedMemorySize, SMFUSE);

    // ---------- prep: weights + sort ----------
    prep_all<<<((int)T_ALL + 255) / 256, 256>>>(pe_w1, pe_w2, pn_w1, pn_w2,
                                                dec_w1, enc_w2, dec_w2, dec_b2, eme_w2);
    sort_hist<<<(NEDGE + 255) / 256, 256>>>(dst);
    sort_scan<<<1, 1024>>>();
    sort_scatter<<<(NEDGE + 255) / 256, 256>>>(src, dst, redge);

    // ---------- encoder ----------
    {
        int total = NBATCH * NMESH * ENC_LDA;
        build_encin<<<(total + 255) / 256, 256>>>(xc, xp, geo, g2m, encin);
    }
    sgemm_bias<128,128,16,8,8><<<gemm_grid(NBATCH*NMESH, HIDD, 128, 128), 256>>>(
        encin, ENC_LDA, enc_w1, enc_b1, nullptr, h, NBATCH*NMESH, HIDD, ENC_IN, 1);
    mma_gemm<256,2,64,2,8,0,false,false,false><<<dim3(4, (NBATCH*NMESH + 127)/128), 256, SM64N>>>(
        h, nullptr, nullptr, en2hi, en2lo, enc_b2, nullptr, x, nullptr,
        NBATCH*NMESH, NODE_D, NODE_D, NODE_D);

    // ---------- edge embedder (sorted edge space) ----------
    sgemm_bias<128,64,16,8,4><<<gemm_grid(NEDGE, EDGE_D, 128, 64), 256>>>(
        redgeS, 4, eme_w1, eme_b1, nullptr, h, NEDGE, EDGE_D, 4, 1);
    mma_gemm<256,2,64,2,1,0,false,false,false><<<dim3(1, NEDGE/128), 256, SM64N>>>(
        h, nullptr, nullptr, em2hi, em2lo, eme_b2, nullptr, e0, nullptr,
        NEDGE, EDGE_D, EDGE_D, EDGE_D);

    // ---------- GNN layers (both batches per launch) ----------
    const int MN = NBATCH * NMESH;   // 20484
    for (int l = 0; l < NLAYERS; l++) {
        const float* ein = (l == 0) ? e0 : e;
        size_t einStride = (l == 0) ? 0 : (size_t)NEDGE * EDGE_D;

        // xsd = x @ [Wsrc | Wdst]  (M=20484, K=256, N=1024); also zeroes agg
        mma_gemm<256,2,64,2,4,0,false,false,true><<<dim3(16, (MN+127)/128), 256, SM64N>>>(
            x, nullptr, nullptr,
            wsdhi + (size_t)l*256*1024, wsdlo + (size_t)l*256*1024,
            zeros, nullptr, xsd, agg, MN, 1024, 1024, 1024);

        // fused edge MLP for both batches (dst-sorted, 2 CTAs/SM)
        fused_edge<<<dim3(NEDGE/128, NBATCH), 256, SMFUSE>>>(
            ein, xsd, srcS, dstS,
            pe1hi + (size_t)l*576*HIDD, pe1lo + (size_t)l*576*HIDD,
            pe2hi + (size_t)l*HIDD*EDGE_D, pe2lo + (size_t)l*HIDD*EDGE_D,
            pe_b1 + (size_t)l*HIDD, pe_b2 + (size_t)l*EDGE_D,
            e, agg, einStride);

        // node MLP1: [x | agg] @ W1 + b, relu  (M=20484)
        mma_gemm<256,2,64,2,5,2,true,false,false><<<dim3(8, (MN+127)/128), 256, SM64N>>>(
            x, agg, nullptr,
            pn1hi + (size_t)l*320*HIDD, pn1lo + (size_t)l*320*HIDD,
            pn_b1 + (size_t)l*HIDD, nullptr, h, nullptr, MN, HIDD, HIDD, HIDD);
        // node MLP2: h @ W2 + b + x (in place, M=20484)
        mma_gemm<256,2,64,2,8,0,false,true,false><<<dim3(4, (MN+127)/128), 256, SM64N>>>(
            h, nullptr, nullptr,
            pn2hi + (size_t)l*HIDD*NODE_D, pn2lo + (size_t)l*HIDD*NODE_D,
            pn_b2 + (size_t)l*NODE_D, x, x, nullptr, MN, NODE_D, NODE_D, NODE_D);
    }

    // ---------- decoder ----------
    mma_gemm<256,2,64,2,4,4,true,false,false><<<dim3(8, (NBATCH*NGRID+127)/128), 256, SM64N>>>(
        x, nullptr, m2g,
        dc1hi, dc1lo, dec_b1, nullptr,
        h, nullptr, NBATCH*NGRID, HIDD, HIDD, HIDD);
    mma_gemm<256,1,80,1,8,0,false,false,false><<<dim3(1, (NBATCH*NGRID + 127)/128), 256, SM80>>>(
        h, nullptr, nullptr, dc2hi, dc2lo, dcb2p, nullptr, out, nullptr,
        NBATCH*NGRID, 80, 78, 78);
}

// round 16
// speedup vs baseline: 1.0246x; 1.0078x over previous
#include <cuda_runtime.h>
#include <cuda_bf16.h>
#include <cstdint>

// ---------------- problem constants ----------------
#define NLAT   181
#define NLON   360
#define NV     78
#define NGRID  (NLAT*NLON)      // 65160
#define NBATCH 2
#define NMESH  10242
#define NEDGE  163840
#define NODE_D 256
#define EDGE_D 64
#define HIDD   512
#define NLAYERS 16
#define ENC_IN  163
#define ENC_K   192             // padded K for HMMA encoder MLP1

// ---------------- device scratch ----------------
__device__ float g_encin[(size_t)NBATCH*NMESH*ENC_K];
__device__ float g_x    [(size_t)NBATCH*NMESH*NODE_D];
__device__ float g_e    [(size_t)NBATCH*NEDGE*EDGE_D];
__device__ float g_e0   [(size_t)NEDGE*EDGE_D];
__device__ float g_h    [(size_t)NEDGE*HIDD];
__device__ float g_agg  [(size_t)NBATCH*NMESH*EDGE_D];
__device__ float g_xsd  [(size_t)NBATCH*NMESH*1024];
__device__ float g_zeros[1024];
__device__ float g_dcb2p[80];
// edge sort (dst-sorted order; edge state lives in sorted space forever)
__device__ int   g_cnt  [NMESH];
__device__ int   g_off  [NMESH];
__device__ int   g_srcS [NEDGE];
__device__ int   g_dstS [NEDGE];
__device__ float g_redgeS[(size_t)NEDGE*4];
// bf16 hi/lo split weights
__device__ __nv_bfloat16 g_pe1hi[(size_t)NLAYERS*576*HIDD];
__device__ __nv_bfloat16 g_pe1lo[(size_t)NLAYERS*576*HIDD];
__device__ __nv_bfloat16 g_wsdhi[(size_t)NLAYERS*256*1024];
__device__ __nv_bfloat16 g_wsdlo[(size_t)NLAYERS*256*1024];
__device__ __nv_bfloat16 g_pe2hi[(size_t)NLAYERS*HIDD*EDGE_D];
__device__ __nv_bfloat16 g_pe2lo[(size_t)NLAYERS*HIDD*EDGE_D];
__device__ __nv_bfloat16 g_pn1hi[(size_t)NLAYERS*320*HIDD];
__device__ __nv_bfloat16 g_pn1lo[(size_t)NLAYERS*320*HIDD];
__device__ __nv_bfloat16 g_pn2hi[(size_t)NLAYERS*HIDD*NODE_D];
__device__ __nv_bfloat16 g_pn2lo[(size_t)NLAYERS*HIDD*NODE_D];
__device__ __nv_bfloat16 g_dc1hi[(size_t)NODE_D*HIDD];
__device__ __nv_bfloat16 g_dc1lo[(size_t)NODE_D*HIDD];
__device__ __nv_bfloat16 g_dc2hi[(size_t)HIDD*80];
__device__ __nv_bfloat16 g_dc2lo[(size_t)HIDD*80];
__device__ __nv_bfloat16 g_en1hi[(size_t)ENC_K*HIDD];
__device__ __nv_bfloat16 g_en1lo[(size_t)ENC_K*HIDD];
__device__ __nv_bfloat16 g_en2hi[(size_t)HIDD*NODE_D];
__device__ __nv_bfloat16 g_en2lo[(size_t)HIDD*NODE_D];
__device__ __nv_bfloat16 g_em2hi[(size_t)EDGE_D*EDGE_D];
__device__ __nv_bfloat16 g_em2lo[(size_t)EDGE_D*EDGE_D];

// ---------------- asm helpers ----------------
__device__ __forceinline__ void ldsm_x4(uint32_t* r, uint32_t addr) {
    asm volatile("ldmatrix.sync.aligned.m8n8.x4.shared.b16 {%0,%1,%2,%3}, [%4];"
        : "=r"(r[0]), "=r"(r[1]), "=r"(r[2]), "=r"(r[3]) : "r"(addr));
}
__device__ __forceinline__ void ldsm_x4t(uint32_t* r, uint32_t addr) {
    asm volatile("ldmatrix.sync.aligned.m8n8.x4.trans.shared.b16 {%0,%1,%2,%3}, [%4];"
        : "=r"(r[0]), "=r"(r[1]), "=r"(r[2]), "=r"(r[3]) : "r"(addr));
}
__device__ __forceinline__ void mma16816(float* d, const uint32_t* a, const uint32_t* b) {
    asm volatile("mma.sync.aligned.m16n8k16.row.col.f32.bf16.bf16.f32 "
        "{%0,%1,%2,%3}, {%4,%5,%6,%7}, {%8,%9}, {%0,%1,%2,%3};"
        : "+f"(d[0]), "+f"(d[1]), "+f"(d[2]), "+f"(d[3])
        : "r"(a[0]), "r"(a[1]), "r"(a[2]), "r"(a[3]), "r"(b[0]), "r"(b[1]));
}
__device__ __forceinline__ uint32_t smem_u32(const void* p) {
    uint32_t a;
    asm("{ .reg .u64 t; cvta.to.shared.u64 t, %1; cvt.u32.u64 %0, t; }" : "=r"(a) : "l"(p));
    return a;
}
#define CP_ASYNC16(dst, src) \
    asm volatile("cp.async.cg.shared.global [%0], [%1], 16;" :: "r"(dst), "l"(src))
#define CP_COMMIT() asm volatile("cp.async.commit_group;" ::: "memory")
#define CP_WAIT0()  asm volatile("cp.async.wait_group 0;" ::: "memory")
#define STS_V2(addr, x, y) \
    asm volatile("st.shared.v2.u32 [%0], {%1,%2};" :: "r"(addr), "r"(x), "r"(y))
#define STS_U32(addr, x) \
    asm volatile("st.shared.u32 [%0], %1;" :: "r"(addr), "r"(x))

__device__ __forceinline__ void split4(float4 v, uint2& hh, uint2& ll) {
    __nv_bfloat16 h0 = __float2bfloat16_rn(v.x), h1 = __float2bfloat16_rn(v.y);
    __nv_bfloat16 h2 = __float2bfloat16_rn(v.z), h3 = __float2bfloat16_rn(v.w);
    __nv_bfloat16 g0 = __float2bfloat16_rn(v.x - __bfloat162float(h0));
    __nv_bfloat16 g1 = __float2bfloat16_rn(v.y - __bfloat162float(h1));
    __nv_bfloat16 g2 = __float2bfloat16_rn(v.z - __bfloat162float(h2));
    __nv_bfloat16 g3 = __float2bfloat16_rn(v.w - __bfloat162float(h3));
    hh.x = (uint32_t)__bfloat16_as_ushort(h0) | ((uint32_t)__bfloat16_as_ushort(h1) << 16);
    hh.y = (uint32_t)__bfloat16_as_ushort(h2) | ((uint32_t)__bfloat16_as_ushort(h3) << 16);
    ll.x = (uint32_t)__bfloat16_as_ushort(g0) | ((uint32_t)__bfloat16_as_ushort(g1) << 16);
    ll.y = (uint32_t)__bfloat16_as_ushort(g2) | ((uint32_t)__bfloat16_as_ushort(g3) << 16);
}
__device__ __forceinline__ void split2(float vx, float vy, uint32_t& hp, uint32_t& lp) {
    __nv_bfloat16 hx = __float2bfloat16_rn(vx), hy = __float2bfloat16_rn(vy);
    __nv_bfloat16 lx = __float2bfloat16_rn(vx - __bfloat162float(hx));
    __nv_bfloat16 ly = __float2bfloat16_rn(vy - __bfloat162float(hy));
    hp = (uint32_t)__bfloat16_as_ushort(hx) | ((uint32_t)__bfloat16_as_ushort(hy) << 16);
    lp = (uint32_t)__bfloat16_as_ushort(lx) | ((uint32_t)__bfloat16_as_ushort(ly) << 16);
}

// ---------------- A-gather modes ----------------
// MODE 0: plain A[M][K]
// MODE 2: [x(256)|agg(64)]
// MODE 4: gathered rows A[m2g[g%NGRID] + (g/NGRID)*NMESH][256]
template<int MODE, int AIT, int RPI>
__device__ __forceinline__ void prefA(float4 (&Ra)[AIT], int c, int rowBase, int M,
    const float* __restrict__ A, const float* __restrict__ aux,
    const int (&sI)[AIT], int tid, int K)
{
    const int f = tid & 15;
    #pragma unroll
    for (int it = 0; it < AIT; it++) {
        int gr = rowBase + it * RPI + (tid >> 4);
        if (gr < M) {
            const float* p;
            if (MODE == 0)      p = A + (size_t)gr * K + c * 64;
            else if (MODE == 2) p = (c < 4) ? A + (size_t)gr * 256 + c * 64
                                            : aux + (size_t)gr * 64;
            else                p = A + (size_t)sI[it] * 256 + c * 64;
            Ra[it] = reinterpret_cast<const float4*>(p)[f];
        } else {
            Ra[it] = make_float4(0.f, 0.f, 0.f, 0.f);
        }
    }
}

// =====================================================================
//  HMMA GEMM: C[M x Nclip (pitch Cpitch)] = [res+] relu?(gather(A)@W + bias)
//  256 threads, BN=64, MINB=2 -> 110.6 KB smem, 2 CTAs/SM.
//  ZAGG: CTAs in column 0 also zero zbuf rows.
// =====================================================================
template<int THREADS, int MINB, int BN, int WARPS_N, int NC, int MODE,
         bool RELU, bool HAS_RES, bool ZAGG>
__global__ void __launch_bounds__(THREADS, MINB)
mma_gemm(const float* __restrict__ A, const float* __restrict__ aux,
         const int* __restrict__ idx1,
         const __nv_bfloat16* __restrict__ Bhi, const __nv_bfloat16* __restrict__ Blo,
         const float* __restrict__ bias, const float* res, float* C,
         float* zbuf, int M, int Nfull, int Cpitch, int Nclip)
{
    constexpr int K       = NC * 64;
    constexpr int NWARP   = THREADS / 32;
    constexpr int WARPS_M = NWARP / WARPS_N;
    constexpr int WTM     = 128 / WARPS_M;
    constexpr int WTN     = BN / WARPS_N;
    constexpr int MT      = WTM / 16;
    constexpr int NT      = WTN / 8;
    constexpr int ASTRIDE = 72;
    constexpr int APLANE  = 128 * ASTRIDE * 2;
    constexpr int ABUF    = 2 * APLANE;
    constexpr int BSTRIDE = BN + 8;
    constexpr int BPLANE  = 64 * BSTRIDE * 2;
    constexpr int BBUF    = 2 * BPLANE;
    constexpr int GRAN    = BN / 8;
    constexpr int BTOT    = 2 * 64 * GRAN;
    constexpr int AIT     = 2048 / THREADS;
    constexpr int RPI     = THREADS / 16;
    static_assert((BTOT % THREADS) == 0, "B loader divisibility");

    extern __shared__ char sm[];
    const uint32_t smA = smem_u32(sm);
    const uint32_t smB = smA + 2 * ABUF;

    const int tid    = threadIdx.x;
    const int lane   = tid & 31;
    const int wid    = tid >> 5;
    const int warp_n = wid % WARPS_N;
    const int warp_m = wid / WARPS_N;
    const int rowBase = blockIdx.y * 128;
    const int colBase = blockIdx.x * BN;

    if (ZAGG && blockIdx.x == 0) {
        #pragma unroll
        for (int it = 0; it < 2048 / THREADS; it++) {
            int i = tid + it * THREADS;
            int r = rowBase + (i >> 4);
            if (r < M)
                reinterpret_cast<float4*>(zbuf)[(size_t)r * 16 + (i & 15)] =
                    make_float4(0.f, 0.f, 0.f, 0.f);
        }
    }

    int sI[AIT];
    #pragma unroll
    for (int it = 0; it < AIT; it++) {
        int gr = rowBase + it * RPI + (tid >> 4);
        int g  = (gr < M) ? gr : 0;
        if (MODE == 4) {
            int b = g / NGRID;
            sI[it] = idx1[g - b * NGRID] + b * NMESH;
        } else {
            sI[it] = 0;
        }
    }

    float acc[MT][NT][4];
    #pragma unroll
    for (int i = 0; i < MT; i++)
        #pragma unroll
        for (int j = 0; j < NT; j++)
            #pragma unroll
            for (int q = 0; q < 4; q++) acc[i][j][q] = 0.f;

    float4 Ra[AIT];
    prefA<MODE, AIT, RPI>(Ra, 0, rowBase, M, A, aux, sI, tid, K);

    {
        #pragma unroll
        for (int it = 0; it < BTOT / THREADS; it++) {
            int i = it * THREADS + tid;
            int plane = i / (64 * GRAN);
            int rem   = i % (64 * GRAN);
            int k = rem / GRAN, g = rem % GRAN;
            const __nv_bfloat16* sp = (plane ? Blo : Bhi)
                + (size_t)k * Nfull + colBase + g * 8;
            CP_ASYNC16(smB + plane * BPLANE + (uint32_t)(k * BSTRIDE + g * 8) * 2, sp);
        }
        CP_COMMIT();
    }

    for (int c = 0; c < NC; c++) {
        const int buf = c & 1;
        #pragma unroll
        for (int it = 0; it < AIT; it++) {
            int r = it * RPI + (tid >> 4);
            int f = tid & 15;
            uint2 hh, ll;
            split4(Ra[it], hh, ll);
            uint32_t off = smA + buf * ABUF + (uint32_t)(r * ASTRIDE + f * 4) * 2;
            STS_V2(off, hh.x, hh.y);
            STS_V2(off + APLANE, ll.x, ll.y);
        }
        if (c + 1 < NC) prefA<MODE, AIT, RPI>(Ra, c + 1, rowBase, M, A, aux, sI, tid, K);
        CP_WAIT0();
        __syncthreads();
        if (c + 1 < NC) {
            #pragma unroll
            for (int it = 0; it < BTOT / THREADS; it++) {
                int i = it * THREADS + tid;
                int plane = i / (64 * GRAN);
                int rem   = i % (64 * GRAN);
                int k = rem / GRAN, g = rem % GRAN;
                const __nv_bfloat16* sp = (plane ? Blo : Bhi)
                    + (size_t)(c + 1) * 64 * Nfull + (size_t)k * Nfull + colBase + g * 8;
                CP_ASYNC16(smB + (1 - buf) * BBUF + plane * BPLANE
                           + (uint32_t)(k * BSTRIDE + g * 8) * 2, sp);
            }
            CP_COMMIT();
        }

        #pragma unroll
        for (int ks = 0; ks < 4; ks++) {
            uint32_t Ah[MT][4], Al[MT][4];
            #pragma unroll
            for (int mt = 0; mt < MT; mt++) {
                uint32_t addr = smA + buf * ABUF
                    + (uint32_t)((warp_m * WTM + mt * 16 + (lane & 15)) * ASTRIDE
                                 + ks * 16 + (lane >> 4) * 8) * 2;
                ldsm_x4(Ah[mt], addr);
                ldsm_x4(Al[mt], addr + APLANE);
            }
            uint32_t Bh[(NT + 1) / 2][4], Bl[(NT + 1) / 2][4];
            #pragma unroll
            for (int np = 0; np < NT / 2; np++) {
                uint32_t addr = smB + buf * BBUF
                    + (uint32_t)((ks * 16 + (lane & 15)) * BSTRIDE
                                 + warp_n * WTN + np * 16 + (lane >> 4) * 8) * 2;
                ldsm_x4t(Bh[np], addr);
                ldsm_x4t(Bl[np], addr + BPLANE);
            }
            #pragma unroll
            for (int mt = 0; mt < MT; mt++)
                #pragma unroll
                for (int nt = 0; nt < NT; nt++) {
                    const uint32_t* bh = &Bh[nt >> 1][(nt & 1) * 2];
                    const uint32_t* bl = &Bl[nt >> 1][(nt & 1) * 2];
                    mma16816(acc[mt][nt], Ah[mt], bh);
                    mma16816(acc[mt][nt], Ah[mt], bl);
                    mma16816(acc[mt][nt], Al[mt], bh);
                }
        }
    }

    #pragma unroll
    for (int nt = 0; nt < NT; nt++) {
        int n = colBase + warp_n * WTN + nt * 8 + (lane & 3) * 2;
        if (n >= Nclip) continue;
        float2 bb = *reinterpret_cast<const float2*>(bias + n);
        #pragma unroll
        for (int mt = 0; mt < MT; mt++) {
            #pragma unroll
            for (int half = 0; half < 2; half++) {
                int row = rowBase + warp_m * WTM + mt * 16 + (lane >> 2) + half * 8;
                if (row < M) {
                    float vx = acc[mt][nt][half * 2 + 0] + bb.x;
                    float vy = acc[mt][nt][half * 2 + 1] + bb.y;
                    size_t off = (size_t)row * Cpitch + n;
                    if (HAS_RES) {
                        float2 rr = *reinterpret_cast<const float2*>(res + off);
                        vx += rr.x; vy += rr.y;
                    }
                    if (RELU) { vx = fmaxf(vx, 0.f); vy = fmaxf(vy, 0.f); }
                    float2 o; o.x = vx; o.y = vy;
                    *reinterpret_cast<float2*>(C + off) = o;
                }
            }
        }
    }
}

// =====================================================================
//  Fused edge layer (batched via blockIdx.y, edges dst-sorted):
//  256 threads / 8 warps, 110.6 KB smem -> 2 CTAs/SM.
// =====================================================================
__global__ void __launch_bounds__(256, 2)
fused_edge(const float* __restrict__ ein,
           const float* __restrict__ xsd,
           const int* __restrict__ src, const int* __restrict__ dst,
           const __nv_bfloat16* __restrict__ W1hi, const __nv_bfloat16* __restrict__ W1lo,
           const __nv_bfloat16* __restrict__ W2hi, const __nv_bfloat16* __restrict__ W2lo,
           const float* __restrict__ b1, const float* __restrict__ b2,
           float* __restrict__ eout, float* __restrict__ agg,
           size_t einBatchStride)
{
    constexpr int A_STR  = 72;
    constexpr int A_PL   = 128 * A_STR * 2;
    constexpr int OFF_A  = 0;
    constexpr int B1_STR = 72;
    constexpr int B1_PL  = 64 * B1_STR * 2;
    constexpr int OFF_B1 = 2 * A_PL;
    constexpr int H_STR  = 72;
    constexpr int H_PL   = 128 * H_STR * 2;
    constexpr int OFF_H  = OFF_B1 + 2 * B1_PL;
    constexpr int B2_STR = 72;
    constexpr int B2_PL  = 64 * B2_STR * 2;
    constexpr int OFF_B2 = OFF_H + 2 * H_PL;   // total 110592

    extern __shared__ char sm[];
    const uint32_t base = smem_u32(sm);

    const int tid  = threadIdx.x;
    const int lane = tid & 31;
    const int wid  = tid >> 5;
    const int warp_m = wid >> 1;
    const int warp_n = wid & 1;
    const int rowBase = blockIdx.x * 128;
    const int batch   = blockIdx.y;

    const float* einb = ein + (size_t)batch * einBatchStride;
    const float* xsdb = xsd + (size_t)batch * NMESH * 1024;
    float* eoutb = eout + (size_t)batch * NEDGE * EDGE_D;
    float* aggb  = agg  + (size_t)batch * NMESH * EDGE_D;

    int sidx[2][2], didx[2][2];
    #pragma unroll
    for (int mt = 0; mt < 2; mt++)
        #pragma unroll
        for (int half = 0; half < 2; half++) {
            int g = rowBase + warp_m * 32 + mt * 16 + (lane >> 2) + half * 8;
            sidx[mt][half] = src[g];
            didx[mt][half] = dst[g];
        }

    {
        const float4* E4 = reinterpret_cast<const float4*>(einb + (size_t)rowBase * 64);
        #pragma unroll
        for (int it = 0; it < 8; it++) {
            int i = tid + it * 256;
            int r = i >> 4, f = i & 15;
            float4 v = E4[r * 16 + f];
            uint2 hh, ll;
            split4(v, hh, ll);
            uint32_t off = base + OFF_A + (uint32_t)(r * A_STR + f * 4) * 2;
            STS_V2(off, hh.x, hh.y);
            STS_V2(off + A_PL, ll.x, ll.y);
        }
    }

    float acc2[2][4][4];
    #pragma unroll
    for (int i = 0; i < 2; i++)
        #pragma unroll
        for (int j = 0; j < 4; j++)
            #pragma unroll
            for (int q = 0; q < 4; q++) acc2[i][j][q] = 0.f;

    for (int nc = 0; nc < 8; nc++) {
        __syncthreads();
        #pragma unroll
        for (int it = 0; it < 4; it++) {
            int i = tid + it * 256;
            int plane = i >> 9;
            int rem = i & 511;
            int k = rem >> 3, g = rem & 7;
            const __nv_bfloat16* sp = (plane ? W1lo : W1hi)
                + (size_t)k * 512 + nc * 64 + g * 8;
            CP_ASYNC16(base + OFF_B1 + plane * B1_PL + (uint32_t)(k * B1_STR + g * 8) * 2, sp);
        }
        #pragma unroll
        for (int it = 0; it < 4; it++) {
            int i = tid + it * 256;
            int plane = i >> 9;
            int rem = i & 511;
            int k = rem >> 3, g = rem & 7;
            const __nv_bfloat16* sp = (plane ? W2lo : W2hi)
                + (size_t)(nc * 64 + k) * 64 + g * 8;
            CP_ASYNC16(base + OFF_B2 + plane * B2_PL + (uint32_t)(k * B2_STR + g * 8) * 2, sp);
        }
        CP_COMMIT();
        CP_WAIT0();
        __syncthreads();

        float acc1[2][4][4];
        #pragma unroll
        for (int i = 0; i < 2; i++)
            #pragma unroll
            for (int j = 0; j < 4; j++)
                #pragma unroll
                for (int q = 0; q < 4; q++) acc1[i][j][q] = 0.f;

        #pragma unroll
        for (int ks = 0; ks < 4; ks++) {
            uint32_t Ah[2][4], Al[2][4];
            #pragma unroll
            for (int mt = 0; mt < 2; mt++) {
                uint32_t addr = base + OFF_A
                    + (uint32_t)((warp_m * 32 + mt * 16 + (lane & 15)) * A_STR
                                 + ks * 16 + (lane >> 4) * 8) * 2;
                ldsm_x4(Ah[mt], addr);
                ldsm_x4(Al[mt], addr + A_PL);
            }
            uint32_t Bh[2][4], Bl[2][4];
            #pragma unroll
            for (int np = 0; np < 2; np++) {
                uint32_t addr = base + OFF_B1
                    + (uint32_t)((ks * 16 + (lane & 15)) * B1_STR
                                 + warp_n * 32 + np * 16 + (lane >> 4) * 8) * 2;
                ldsm_x4t(Bh[np], addr);
                ldsm_x4t(Bl[np], addr + B1_PL);
            }
            #pragma unroll
            for (int mt = 0; mt < 2; mt++)
                #pragma unroll
                for (int nt = 0; nt < 4; nt++) {
                    const uint32_t* bh = &Bh[nt >> 1][(nt & 1) * 2];
                    const uint32_t* bl = &Bl[nt >> 1][(nt & 1) * 2];
                    mma16816(acc1[mt][nt], Ah[mt], bh);
                    mma16816(acc1[mt][nt], Ah[mt], bl);
                    mma16816(acc1[mt][nt], Al[mt], bh);
                }
        }

        #pragma unroll
        for (int nt = 0; nt < 4; nt++) {
            int col  = warp_n * 32 + nt * 8 + (lane & 3) * 2;
            int gcol = nc * 64 + col;
            float2 bb = *reinterpret_cast<const float2*>(b1 + gcol);
            #pragma unroll
            for (int mt = 0; mt < 2; mt++) {
                #pragma unroll
                for (int half = 0; half < 2; half++) {
                    int row_l = warp_m * 32 + mt * 16 + (lane >> 2) + half * 8;
                    float2 sv = *reinterpret_cast<const float2*>(
                        xsdb + (size_t)sidx[mt][half] * 1024 + gcol);
                    float2 dv = *reinterpret_cast<const float2*>(
                        xsdb + (size_t)didx[mt][half] * 1024 + 512 + gcol);
                    float vx = fmaxf(acc1[mt][nt][half * 2 + 0] + bb.x + sv.x + dv.x, 0.f);
                    float vy = fmaxf(acc1[mt][nt][half * 2 + 1] + bb.y + sv.y + dv.y, 0.f);
                    uint32_t hp, lp;
                    split2(vx, vy, hp, lp);
                    uint32_t off = base + OFF_H + (uint32_t)(row_l * H_STR + col) * 2;
                    STS_U32(off, hp);
                    STS_U32(off + H_PL, lp);
                }
            }
        }
        __syncthreads();

        #pragma unroll
        for (int ks = 0; ks < 4; ks++) {
            uint32_t Ah[2][4], Al[2][4];
            #pragma unroll
            for (int mt = 0; mt < 2; mt++) {
                uint32_t addr = base + OFF_H
                    + (uint32_t)((warp_m * 32 + mt * 16 + (lane & 15)) * H_STR
                                 + ks * 16 + (lane >> 4) * 8) * 2;
                ldsm_x4(Ah[mt], addr);
                ldsm_x4(Al[mt], addr + H_PL);
            }
            uint32_t Bh[2][4], Bl[2][4];
            #pragma unroll
            for (int np = 0; np < 2; np++) {
                uint32_t addr = base + OFF_B2
                    + (uint32_t)((ks * 16 + (lane & 15)) * B2_STR
                                 + warp_n * 32 + np * 16 + (lane >> 4) * 8) * 2;
                ldsm_x4t(Bh[np], addr);
                ldsm_x4t(Bl[np], addr + B2_PL);
            }
            #pragma unroll
            for (int mt = 0; mt < 2; mt++)
                #pragma unroll
                for (int nt = 0; nt < 4; nt++) {
                    const uint32_t* bh = &Bh[nt >> 1][(nt & 1) * 2];
                    const uint32_t* bl = &Bl[nt >> 1][(nt & 1) * 2];
                    mma16816(acc2[mt][nt], Ah[mt], bh);
                    mma16816(acc2[mt][nt], Ah[mt], bl);
                    mma16816(acc2[mt][nt], Al[mt], bh);
                }
        }
    }

    __syncthreads();
    float* stage = reinterpret_cast<float*>(sm);
    int*   sdst  = reinterpret_cast<int*>(sm + 33280);
    if (tid < 128) sdst[tid] = dst[rowBase + tid];

    #pragma unroll
    for (int nt = 0; nt < 4; nt++) {
        int n = warp_n * 32 + nt * 8 + (lane & 3) * 2;
        float2 bb = *reinterpret_cast<const float2*>(b2 + n);
        #pragma unroll
        for (int mt = 0; mt < 2; mt++) {
            #pragma unroll
            for (int half = 0; half < 2; half++) {
                int row_l = warp_m * 32 + mt * 16 + (lane >> 2) + half * 8;
                size_t off = (size_t)(rowBase + row_l) * 64 + n;
                float2 rr = *reinterpret_cast<const float2*>(einb + off);
                float vx = acc2[mt][nt][half * 2 + 0] + bb.x + rr.x;
                float vy = acc2[mt][nt][half * 2 + 1] + bb.y + rr.y;
                float2 o; o.x = vx; o.y = vy;
                *reinterpret_cast<float2*>(eoutb + off) = o;
                stage[row_l * 65 + n]     = vx;
                stage[row_l * 65 + n + 1] = vy;
            }
        }
    }
    __syncthreads();

    {
        int col = tid & 63;
        int seg = tid >> 6;
        int r0  = seg * 32;
        float sum = 0.f;
        int cur = sdst[r0];
        for (int r = r0; r < r0 + 32; r++) {
            int d  = sdst[r];
            float v = stage[r * 65 + col];
            if (d != cur) {
                atomicAdd(aggb + (size_t)cur * 64 + col, sum);
                sum = 0.f;
                cur = d;
            }
            sum += v;
        }
        atomicAdd(aggb + (size_t)cur * 64 + col, sum);
    }
}

// =====================================================================
//  Weight prep — single kernel
// =====================================================================
__device__ __forceinline__ void splitStore(float v, __nv_bfloat16* hi,
                                           __nv_bfloat16* lo, int i) {
    __nv_bfloat16 h = __float2bfloat16_rn(v);
    hi[i] = h;
    lo[i] = __float2bfloat16_rn(v - __bfloat162float(h));
}

#define T_PE1 (NLAYERS*576*HIDD)
#define T_WSD (NLAYERS*256*1024)
#define T_PE2 (NLAYERS*HIDD*EDGE_D)
#define T_PN1 (NLAYERS*320*HIDD)
#define T_PN2 (NLAYERS*HIDD*NODE_D)
#define T_DC1 (NODE_D*HIDD)
#define T_EN1 (ENC_K*HIDD)
#define T_EN2 (HIDD*NODE_D)
#define T_DC2 (HIDD*80)
#define T_EM2 (EDGE_D*EDGE_D)
#define T_ALL (T_PE1+T_WSD+T_PE2+T_PN1+T_PN2+T_DC1+T_EN1+T_EN2+T_DC2+T_EM2+80+NMESH)

__global__ void prep_all(const float* __restrict__ pe_w1, const float* __restrict__ pe_w2,
                         const float* __restrict__ pn_w1, const float* __restrict__ pn_w2,
                         const float* __restrict__ dec_w1, const float* __restrict__ enc_w2,
                         const float* __restrict__ dec_w2, const float* __restrict__ dec_b2,
                         const float* __restrict__ eme_w2, const float* __restrict__ enc_w1)
{
    int i = blockIdx.x * blockDim.x + threadIdx.x;
    if (i < T_PE1) { splitStore(pe_w1[i], g_pe1hi, g_pe1lo, i); return; }
    i -= T_PE1;
    if (i < T_WSD) {
        int l = i >> 18, rem = i & 262143;
        int r = rem >> 10, n = rem & 1023;
        int srow = (n < 512) ? (64 + r) : (320 + r);
        float v = pe_w1[(size_t)l * 576 * 512 + (size_t)srow * 512 + (n & 511)];
        splitStore(v, g_wsdhi, g_wsdlo, i);
        return;
    }
    i -= T_WSD;
    if (i < T_PE2) { splitStore(pe_w2[i], g_pe2hi, g_pe2lo, i); return; }
    i -= T_PE2;
    if (i < T_PN1) { splitStore(pn_w1[i], g_pn1hi, g_pn1lo, i); return; }
    i -= T_PN1;
    if (i < T_PN2) { splitStore(pn_w2[i], g_pn2hi, g_pn2lo, i); return; }
    i -= T_PN2;
    if (i < T_DC1) { splitStore(dec_w1[i], g_dc1hi, g_dc1lo, i); return; }
    i -= T_DC1;
    if (i < T_EN1) {
        int k = i / HIDD, n = i % HIDD;
        splitStore((k < ENC_IN) ? enc_w1[k * HIDD + n] : 0.f, g_en1hi, g_en1lo, i);
        return;
    }
    i -= T_EN1;
    if (i < T_EN2) { splitStore(enc_w2[i], g_en2hi, g_en2lo, i); return; }
    i -= T_EN2;
    if (i < T_DC2) {
        int k = i / 80, n = i % 80;
        splitStore((n < 78) ? dec_w2[k * 78 + n] : 0.f, g_dc2hi, g_dc2lo, i);
        return;
    }
    i -= T_DC2;
    if (i < T_EM2) { splitStore(eme_w2[i], g_em2hi, g_em2lo, i); return; }
    i -= T_EM2;
    if (i < 80) { g_dcb2p[i] = (i < 78) ? dec_b2[i] : 0.f; return; }
    i -= 80;
    if (i < NMESH) g_cnt[i] = 0;
}

// =====================================================================
//  Edge counting sort (by dst)
// =====================================================================
__global__ void sort_hist(const int* __restrict__ dst) {
    int j = blockIdx.x * blockDim.x + threadIdx.x;
    if (j < NEDGE) atomicAdd(&g_cnt[dst[j]], 1);
}

__global__ void __launch_bounds__(1024) sort_scan() {
    __shared__ int part[1024];
    const int tid = threadIdx.x;
    const int PER = (NMESH + 1023) / 1024;
    int local[11];
    int s = 0;
    #pragma unroll
    for (int i = 0; i < PER; i++) {
        int b = tid * PER + i;
        int c = (b < NMESH) ? g_cnt[b] : 0;
        local[i] = s;
        s += c;
    }
    part[tid] = s;
    __syncthreads();
    for (int off = 1; off < 1024; off <<= 1) {
        int v = (tid >= off) ? part[tid - off] : 0;
        __syncthreads();
        part[tid] += v;
        __syncthreads();
    }
    int excl = (tid == 0) ? 0 : part[tid - 1];
    #pragma unroll
    for (int i = 0; i < PER; i++) {
        int b = tid * PER + i;
        if (b < NMESH) g_off[b] = excl + local[i];
    }
}

__global__ void sort_scatter(const int* __restrict__ src, const int* __restrict__ dst,
                             const float* __restrict__ redge) {
    int j = blockIdx.x * blockDim.x + threadIdx.x;
    if (j >= NEDGE) return;
    int d = dst[j];
    int pos = atomicAdd(&g_off[d], 1);
    g_srcS[pos] = src[j];
    g_dstS[pos] = d;
    float4 rv = reinterpret_cast<const float4*>(redge)[j];
    reinterpret_cast<float4*>(g_redgeS)[pos] = rv;
}

// =====================================================================
//  SIMT fp32 GEMM (embedder MLP1 only)
// =====================================================================
template<int BM, int BN, int BK, int TM, int TN>
__global__ void __launch_bounds__(256)
sgemm_bias(const float* __restrict__ A, int lda,
           const float* __restrict__ W,
           const float* __restrict__ bias,
           const float* res, float* C,
           int M, int N, int K, int doRelu)
{
    constexpr int GN      = TN / 4;
    constexpr int CSTRIDE = BN / GN;
    constexpr int NTC     = BN / TN;
    constexpr int THREADS = (BM / TM) * NTC;
    static_assert(THREADS == 256, "expect 256 threads");
    static_assert(BK == 16 && THREADS == BM * 2, "A loader mapping");

    __shared__ float As[BK][BM + 4];
    __shared__ float Bs[BK][BN];

    const int tid  = threadIdx.x;
    const int tcol = tid % NTC;
    const int trow = tid / NTC;
    const int rowBase = blockIdx.y * BM;
    const int colBase = blockIdx.x * BN;

    float acc[TM][TN];
    #pragma unroll
    for (int i = 0; i < TM; i++)
        #pragma unroll
        for (int j = 0; j < TN; j++) acc[i][j] = 0.f;

    const int am = tid >> 1;
    const int ah = (tid & 1) * 8;

    for (int k0 = 0; k0 < K; k0 += BK) {
        {
            const int gm = rowBase + am;
            const bool mok = (gm < M);
            const float* Arow = A + (size_t)gm * lda + (k0 + ah);
            #pragma unroll
            for (int i = 0; i < 8; i++) {
                int gk = k0 + ah + i;
                As[ah + i][am] = (mok && gk < K) ? Arow[i] : 0.f;
            }
        }
        #pragma unroll
        for (int it = 0; it < (BK * BN) / THREADS; it++) {
            int idx = tid + it * THREADS;
            int k = idx / BN, n = idx % BN;
            int gk = k0 + k, gn = colBase + n;
            Bs[k][n] = (gk < K && gn < N) ? W[(size_t)gk * N + gn] : 0.f;
        }
        __syncthreads();

        #pragma unroll
        for (int k = 0; k < BK; k++) {
            float ra[TM], rb[TN];
            #pragma unroll
            for (int i = 0; i < TM; i++) ra[i] = As[k][trow * TM + i];
            #pragma unroll
            for (int cg = 0; cg < GN; cg++)
                #pragma unroll
                for (int j = 0; j < 4; j++)
                    rb[cg * 4 + j] = Bs[k][cg * CSTRIDE + tcol * 4 + j];
            #pragma unroll
            for (int i = 0; i < TM; i++)
                #pragma unroll
                for (int j = 0; j < TN; j++)
                    acc[i][j] = fmaf(ra[i], rb[j], acc[i][j]);
        }
        __syncthreads();
    }

    #pragma unroll
    for (int i = 0; i < TM; i++) {
        int gm = rowBase + trow * TM + i;
        if (gm >= M) continue;
        #pragma unroll
        for (int cg = 0; cg < GN; cg++) {
            #pragma unroll
            for (int j = 0; j < 4; j++) {
                int gn = colBase + cg * CSTRIDE + tcol * 4 + j;
                if (gn >= N) continue;
                float v = acc[i][cg * 4 + j] + bias[gn];
                if (doRelu) v = fmaxf(v, 0.f);
                size_t off = (size_t)gm * N + gn;
                if (res) v += res[off];
                C[off] = v;
            }
        }
    }
}

// ---------------- builders ----------------
__global__ void build_encin(const float* __restrict__ xc, const float* __restrict__ xp,
                            const float* __restrict__ geo, const int* __restrict__ g2m,
                            float* __restrict__ out)
{
    int idx = blockIdx.x * blockDim.x + threadIdx.x;
    const int total = NBATCH * NMESH * ENC_K;
    if (idx >= total) return;
    int row = idx / ENC_K;
    int c   = idx - row * ENC_K;
    int b   = row / NMESH;
    int m   = row - b * NMESH;
    float v = 0.f;
    if (c < NV)            v = xc[((size_t)b * NGRID + g2m[m]) * NV + c];
    else if (c < 2 * NV)   v = xp[((size_t)b * NGRID + g2m[m]) * NV + (c - NV)];
    else if (c < ENC_IN)   v = geo[m * 7 + (c - 2 * NV)];
    out[idx] = v;
}

// ---------------- launcher ----------------
static inline dim3 gemm_grid(int M, int N, int BM, int BN) {
    return dim3((unsigned)((N + BN - 1) / BN), (unsigned)((M + BM - 1) / BM));
}

extern "C" void kernel_launch(void* const* d_in, const int* in_sizes, int n_in,
                              void* d_out, int out_size)
{
    const float* xc     = (const float*)d_in[0];
    const float* xp     = (const float*)d_in[1];
    const float* geo    = (const float*)d_in[2];
    const float* redge  = (const float*)d_in[3];
    const int*   eidx   = (const int*)  d_in[4];
    const int*   g2m    = (const int*)  d_in[5];
    const int*   m2g    = (const int*)  d_in[6];
    const float* enc_w1 = (const float*)d_in[7];
    const float* enc_b1 = (const float*)d_in[8];
    const float* enc_w2 = (const float*)d_in[9];
    const float* enc_b2 = (const float*)d_in[10];
    const float* eme_w1 = (const float*)d_in[11];
    const float* eme_b1 = (const float*)d_in[12];
    const float* eme_w2 = (const float*)d_in[13];
    const float* eme_b2 = (const float*)d_in[14];
    const float* pe_w1  = (const float*)d_in[15];
    const float* pe_b1  = (const float*)d_in[16];
    const float* pe_w2  = (const float*)d_in[17];
    const float* pe_b2  = (const float*)d_in[18];
    const float* pn_w1  = (const float*)d_in[19];
    const float* pn_b1  = (const float*)d_in[20];
    const float* pn_w2  = (const float*)d_in[21];
    const float* pn_b2  = (const float*)d_in[22];
    const float* dec_w1 = (const float*)d_in[23];
    const float* dec_b1 = (const float*)d_in[24];
    const float* dec_w2 = (const float*)d_in[25];
    const float* dec_b2 = (const float*)d_in[26];
    float* out = (float*)d_out;

    float *encin, *x, *e, *e0, *h, *agg, *xsd, *zeros, *dcb2p, *redgeS;
    int *srcS, *dstS;
    __nv_bfloat16 *pe1hi,*pe1lo,*wsdhi,*wsdlo,*pe2hi,*pe2lo,*pn1hi,*pn1lo,*pn2hi,*pn2lo;
    __nv_bfloat16 *dc1hi,*dc1lo,*dc2hi,*dc2lo,*en1hi,*en1lo,*en2hi,*en2lo,*em2hi,*em2lo;
    cudaGetSymbolAddress((void**)&encin, g_encin);
    cudaGetSymbolAddress((void**)&x,     g_x);
    cudaGetSymbolAddress((void**)&e,     g_e);
    cudaGetSymbolAddress((void**)&e0,    g_e0);
    cudaGetSymbolAddress((void**)&h,     g_h);
    cudaGetSymbolAddress((void**)&agg,   g_agg);
    cudaGetSymbolAddress((void**)&xsd,   g_xsd);
    cudaGetSymbolAddress((void**)&zeros, g_zeros);
    cudaGetSymbolAddress((void**)&dcb2p, g_dcb2p);
    cudaGetSymbolAddress((void**)&redgeS,g_redgeS);
    cudaGetSymbolAddress((void**)&srcS,  g_srcS);
    cudaGetSymbolAddress((void**)&dstS,  g_dstS);
    cudaGetSymbolAddress((void**)&pe1hi, g_pe1hi);
    cudaGetSymbolAddress((void**)&pe1lo, g_pe1lo);
    cudaGetSymbolAddress((void**)&wsdhi, g_wsdhi);
    cudaGetSymbolAddress((void**)&wsdlo, g_wsdlo);
    cudaGetSymbolAddress((void**)&pe2hi, g_pe2hi);
    cudaGetSymbolAddress((void**)&pe2lo, g_pe2lo);
    cudaGetSymbolAddress((void**)&pn1hi, g_pn1hi);
    cudaGetSymbolAddress((void**)&pn1lo, g_pn1lo);
    cudaGetSymbolAddress((void**)&pn2hi, g_pn2hi);
    cudaGetSymbolAddress((void**)&pn2lo, g_pn2lo);
    cudaGetSymbolAddress((void**)&dc1hi, g_dc1hi);
    cudaGetSymbolAddress((void**)&dc1lo, g_dc1lo);
    cudaGetSymbolAddress((void**)&dc2hi, g_dc2hi);
    cudaGetSymbolAddress((void**)&dc2lo, g_dc2lo);
    cudaGetSymbolAddress((void**)&en1hi, g_en1hi);
    cudaGetSymbolAddress((void**)&en1lo, g_en1lo);
    cudaGetSymbolAddress((void**)&en2hi, g_en2hi);
    cudaGetSymbolAddress((void**)&en2lo, g_en2lo);
    cudaGetSymbolAddress((void**)&em2hi, g_em2hi);
    cudaGetSymbolAddress((void**)&em2lo, g_em2lo);

    const int* src = eidx;
    const int* dst = eidx + NEDGE;

    constexpr int SM64N  = 2 * (2 * 128 * 72 * 2) + 2 * (2 * 64 * 72 * 2);  // 110592
    constexpr int SM80   = 2 * (2 * 128 * 72 * 2) + 2 * (2 * 64 * 88 * 2);  // 118784
    constexpr int SMFUSE = 110592;

    cudaFuncSetAttribute((const void*)mma_gemm<256,2,64,2,8,0,false,false,false>,
                         cudaFuncAttributeMaxDynamicSharedMemorySize, SM64N);
    cudaFuncSetAttribute((const void*)mma_gemm<256,2,64,2,8,0,false,true,false>,
                         cudaFuncAttributeMaxDynamicSharedMemorySize, SM64N);
    cudaFuncSetAttribute((const void*)mma_gemm<256,2,64,2,5,2,true,false,false>,
                         cudaFuncAttributeMaxDynamicSharedMemorySize, SM64N);
    cudaFuncSetAttribute((const void*)mma_gemm<256,2,64,2,4,4,true,false,false>,
                         cudaFuncAttributeMaxDynamicSharedMemorySize, SM64N);
    cudaFuncSetAttribute((const void*)mma_gemm<256,2,64,2,4,0,false,false,true>,
                         cudaFuncAttributeMaxDynamicSharedMemorySize, SM64N);
    cudaFuncSetAttribute((const void*)mma_gemm<256,2,64,2,3,0,true,false,false>,
                         cudaFuncAttributeMaxDynamicSharedMemorySize, SM64N);
    cudaFuncSetAttribute((const void*)mma_gemm<256,2,64,2,1,0,false,false,false>,
                         cudaFuncAttributeMaxDynamicSharedMemorySize, SM64N);
    cudaFuncSetAttribute((const void*)mma_gemm<256,1,80,1,8,0,false,false,false>,
                         cudaFuncAttributeMaxDynamicSharedMemorySize, SM80);
    cudaFuncSetAttribute((const void*)fused_edge,
                         cudaFuncAttributeMaxDynamicSharedMemorySize, SMFUSE);

    // ---------- prep: weights + sort ----------
    prep_all<<<((int)T_ALL + 255) / 256, 256>>>(pe_w1, pe_w2, pn_w1, pn_w2,
                                                dec_w1, enc_w2, dec_w2, dec_b2,
                                                eme_w2, enc_w1);
    sort_hist<<<(NEDGE + 255) / 256, 256>>>(dst);
    sort_scan<<<1, 1024>>>();
    sort_scatter<<<(NEDGE + 255) / 256, 256>>>(src, dst, redge);

    // ---------- encoder (both MLPs on HMMA) ----------
    {
        int total = NBATCH * NMESH * ENC_K;
        build_encin<<<(total + 255) / 256, 256>>>(xc, xp, geo, g2m, encin);
    }
    mma_gemm<256,2,64,2,3,0,true,false,false><<<dim3(8, (NBATCH*NMESH + 127)/128), 256, SM64N>>>(
        encin, nullptr, nullptr, en1hi, en1lo, enc_b1, nullptr, h, nullptr,
        NBATCH*NMESH, HIDD, HIDD, HIDD);
    mma_gemm<256,2,64,2,8,0,false,false,false><<<dim3(4, (NBATCH*NMESH + 127)/128), 256, SM64N>>>(
        h, nullptr, nullptr, en2hi, en2lo, enc_b2, nullptr, x, nullptr,
        NBATCH*NMESH, NODE_D, NODE_D, NODE_D);

    // ---------- edge embedder (sorted edge space) ----------
    sgemm_bias<128,64,16,8,4><<<gemm_grid(NEDGE, EDGE_D, 128, 64), 256>>>(
        redgeS, 4, eme_w1, eme_b1, nullptr, h, NEDGE, EDGE_D, 4, 1);
    mma_gemm<256,2,64,2,1,0,false,false,false><<<dim3(1, NEDGE/128), 256, SM64N>>>(
        h, nullptr, nullptr, em2hi, em2lo, eme_b2, nullptr, e0, nullptr,
        NEDGE, EDGE_D, EDGE_D, EDGE_D);

    // ---------- GNN layers (both batches per launch) ----------
    const int MN = NBATCH * NMESH;   // 20484
    for (int l = 0; l < NLAYERS; l++) {
        const float* ein = (l == 0) ? e0 : e;
        size_t einStride = (l == 0) ? 0 : (size_t)NEDGE * EDGE_D;

        // xsd = x @ [Wsrc | Wdst]  (M=20484, K=256, N=1024); also zeroes agg
        mma_gemm<256,2,64,2,4,0,false,false,true><<<dim3(16, (MN+127)/128), 256, SM64N>>>(
            x, nullptr, nullptr,
            wsdhi + (size_t)l*256*1024, wsdlo + (size_t)l*256*1024,
            zeros, nullptr, xsd, agg, MN, 1024, 1024, 1024);

        // fused edge MLP for both batches (dst-sorted, 2 CTAs/SM)
        fused_edge<<<dim3(NEDGE/128, NBATCH), 256, SMFUSE>>>(
            ein, xsd, srcS, dstS,
            pe1hi + (size_t)l*576*HIDD, pe1lo + (size_t)l*576*HIDD,
            pe2hi + (size_t)l*HIDD*EDGE_D, pe2lo + (size_t)l*HIDD*EDGE_D,
            pe_b1 + (size_t)l*HIDD, pe_b2 + (size_t)l*EDGE_D,
            e, agg, einStride);

        // node MLP1: [x | agg] @ W1 + b, relu  (M=20484)
        mma_gemm<256,2,64,2,5,2,true,false,false><<<dim3(8, (MN+127)/128), 256, SM64N>>>(
            x, agg, nullptr,
            pn1hi + (size_t)l*320*HIDD, pn1lo + (size_t)l*320*HIDD,
            pn_b1 + (size_t)l*HIDD, nullptr, h, nullptr, MN, HIDD, HIDD, HIDD);
        // node MLP2: h @ W2 + b + x (in place, M=20484)
        mma_gemm<256,2,64,2,8,0,false,true,false><<<dim3(4, (MN+127)/128), 256, SM64N>>>(
            h, nullptr, nullptr,
            pn2hi + (size_t)l*HIDD*NODE_D, pn2lo + (size_t)l*HIDD*NODE_D,
            pn_b2 + (size_t)l*NODE_D, x, x, nullptr, MN, NODE_D, NODE_D, NODE_D);
    }

    // ---------- decoder ----------
    mma_gemm<256,2,64,2,4,4,true,false,false><<<dim3(8, (NBATCH*NGRID+127)/128), 256, SM64N>>>(
        x, nullptr, m2g,
        dc1hi, dc1lo, dec_b1, nullptr,
        h, nullptr, NBATCH*NGRID, HIDD, HIDD, HIDD);
    mma_gemm<256,1,80,1,8,0,false,false,false><<<dim3(1, (NBATCH*NGRID + 127)/128), 256, SM80>>>(
        h, nullptr, nullptr, dc2hi, dc2lo, dcb2p, nullptr, out, nullptr,
        NBATCH*NGRID, 80, 78, 78);
}